// round 1
// baseline (speedup 1.0000x reference)
#include <cuda_runtime.h>
#include <math.h>

// Problem constants
#define BB   16
#define SS   600
#define EE   300
#define HH   512
#define NCC  2
#define DD   180000L          // S*E
#define SE_  180000L          // per-batch n0/x stride
#define SSQ  360000L          // S*S per-batch score stride
#define TT   3

// ---------------- scratch (device globals; no allocation allowed) -------------
__device__ float g_Wx[BB * SS * EE];       // 11.5 MB
__device__ float g_g0[BB * SS * EE];       // 11.5 MB
__device__ float g_P [BB * SS * SS];       // 23 MB
__device__ float g_n0a[BB * SS * EE];
__device__ float g_n0b[BB * SS * EE];
__device__ float g_n1a[BB * HH];
__device__ float g_n1b[BB * HH];
__device__ float g_n2a[BB * NCC];
__device__ float g_n2b[BB * NCC];
__device__ float g_g1 [BB * HH];

// ---------------- generic NT GEMM: C[m,n] = alpha * sum_k A[m,k]*B[n,k] ------
// block tile 64x64, K-tile 16, 256 threads, 4x4 microtile
__global__ __launch_bounds__(256)
void gemm_nt_kernel(const float* __restrict__ A, const float* __restrict__ B,
                    float* __restrict__ C, int M, int N, int K,
                    long sA, long sB, long sC, float alpha)
{
    __shared__ float As[16][68];
    __shared__ float Bs[16][68];
    const float* Ab = A + (long)blockIdx.z * sA;
    const float* Bb = B + (long)blockIdx.z * sB;
    float*       Cb = C + (long)blockIdx.z * sC;
    int t  = threadIdx.x;
    int tx = t & 15, ty = t >> 4;
    int m0 = blockIdx.y * 64, n0 = blockIdx.x * 64;
    int lk = t & 15, lr = t >> 4;
    float acc[4][4] = {};

    for (int k0 = 0; k0 < K; k0 += 16) {
        int kg = k0 + lk;
        bool kin = (kg < K);
#pragma unroll
        for (int j = 0; j < 4; ++j) {
            int r = lr + j * 16;
            int m = m0 + r, n = n0 + r;
            As[lk][r] = (kin && m < M) ? Ab[(long)m * K + kg] : 0.f;
            Bs[lk][r] = (kin && n < N) ? Bb[(long)n * K + kg] : 0.f;
        }
        __syncthreads();
#pragma unroll
        for (int kk = 0; kk < 16; ++kk) {
            float4 av = *(const float4*)&As[kk][ty * 4];
            float4 bv = *(const float4*)&Bs[kk][tx * 4];
            float am[4] = {av.x, av.y, av.z, av.w};
            float bn[4] = {bv.x, bv.y, bv.z, bv.w};
#pragma unroll
            for (int i = 0; i < 4; ++i)
#pragma unroll
                for (int j = 0; j < 4; ++j)
                    acc[i][j] += am[i] * bn[j];
        }
        __syncthreads();
    }
    int n = n0 + tx * 4;
    if (n < N) {
#pragma unroll
        for (int i = 0; i < 4; ++i) {
            int m = m0 + ty * 4 + i;
            if (m < M) {
                float4 o = make_float4(acc[i][0] * alpha, acc[i][1] * alpha,
                                       acc[i][2] * alpha, acc[i][3] * alpha);
                *(float4*)&Cb[(long)m * N + n] = o;
            }
        }
    }
}

// ---------------- generic NN GEMM: C[m,n] = sum_k A[m,k]*B[k,n] --------------
__global__ __launch_bounds__(256)
void gemm_nn_kernel(const float* __restrict__ A, const float* __restrict__ B,
                    float* __restrict__ C, int M, int N, int K,
                    long sA, long sB, long sC)
{
    __shared__ float As[16][68];
    __shared__ float Bs[16][68];
    const float* Ab = A + (long)blockIdx.z * sA;
    const float* Bb = B + (long)blockIdx.z * sB;
    float*       Cb = C + (long)blockIdx.z * sC;
    int t  = threadIdx.x;
    int tx = t & 15, ty = t >> 4;
    int m0 = blockIdx.y * 64, n0 = blockIdx.x * 64;
    int lkA = t & 15, lrA = t >> 4;
    int lnB = t & 63, lkB = t >> 6;
    float acc[4][4] = {};

    for (int k0 = 0; k0 < K; k0 += 16) {
#pragma unroll
        for (int j = 0; j < 4; ++j) {
            int r = lrA + j * 16;
            int m = m0 + r;
            int kg = k0 + lkA;
            As[lkA][r] = (kg < K && m < M) ? Ab[(long)m * K + kg] : 0.f;
        }
#pragma unroll
        for (int j = 0; j < 4; ++j) {
            int kk = lkB + j * 4;
            int kg = k0 + kk;
            int n  = n0 + lnB;
            Bs[kk][lnB] = (kg < K && n < N) ? Bb[(long)kg * N + n] : 0.f;
        }
        __syncthreads();
#pragma unroll
        for (int kk = 0; kk < 16; ++kk) {
            float4 av = *(const float4*)&As[kk][ty * 4];
            float4 bv = *(const float4*)&Bs[kk][tx * 4];
            float am[4] = {av.x, av.y, av.z, av.w};
            float bn[4] = {bv.x, bv.y, bv.z, bv.w};
#pragma unroll
            for (int i = 0; i < 4; ++i)
#pragma unroll
                for (int j = 0; j < 4; ++j)
                    acc[i][j] += am[i] * bn[j];
        }
        __syncthreads();
    }
    int n = n0 + tx * 4;
    if (n < N) {
#pragma unroll
        for (int i = 0; i < 4; ++i) {
            int m = m0 + ty * 4 + i;
            if (m < M) {
                float4 o = make_float4(acc[i][0], acc[i][1], acc[i][2], acc[i][3]);
                *(float4*)&Cb[(long)m * N + n] = o;
            }
        }
    }
}

// ---------------- g0 = Wx + n1 @ W1  (stream W1 once, coalesced over d) ------
// thread handles 2 consecutive d columns, all 16 batches. n1 staged in smem.
__global__ __launch_bounds__(256)
void g0_kernel(const float* __restrict__ n1, const float* __restrict__ W1,
               const float* __restrict__ Wx, float* __restrict__ g0)
{
    __shared__ float n1s[BB * HH];   // 32 KB
    int t = threadIdx.x;
    for (int i = t; i < BB * HH; i += 256) n1s[i] = n1[i];
    __syncthreads();

    long d2 = ((long)blockIdx.x * 256 + t) * 2;
    if (d2 >= DD) return;
    float acc0[BB] = {}, acc1[BB] = {};
    const float* wp = W1 + d2;
#pragma unroll 4
    for (int h = 0; h < HH; ++h) {
        float2 w = *(const float2*)(wp + (long)h * DD);
#pragma unroll
        for (int b = 0; b < BB; ++b) {
            float nv = n1s[b * HH + h];
            acc0[b] += nv * w.x;
            acc1[b] += nv * w.y;
        }
    }
#pragma unroll
    for (int b = 0; b < BB; ++b) {
        long o = (long)b * DD + d2;
        g0[o]     = Wx[o]     + acc0[b];
        g0[o + 1] = Wx[o + 1] + acc1[b];
    }
}

// ---------------- g1 += n0flat @ W1^T  (split-K GEMM M=16,N=512,K=180000) ----
#define G1_KCHUNK 2048L
__global__ __launch_bounds__(256)
void g1_kernel(const float* __restrict__ n0, const float* __restrict__ W1,
               float* __restrict__ g1)
{
    __shared__ float n0s[32][20];     // [kk][b], padded
    __shared__ float ws [32][130];    // [kk][h], padded
    int t  = threadIdx.x;
    int hx = t & 63, by = t >> 6;     // micro: 4 b x 2 h
    int hblk = blockIdx.y * 128;
    long kstart = (long)blockIdx.x * G1_KCHUNK;
    long kend   = kstart + G1_KCHUNK; if (kend > DD) kend = DD;
    float acc[4][2] = {};

    for (long k0 = kstart; k0 < kend; k0 += 32) {
        {   // n0 tile: 16b x 32k
            int kk = t & 31; int b = t >> 5;      // b 0..7
            long kg = k0 + kk;
            float v0 = (kg < DD) ? n0[(long)b * DD + kg] : 0.f;
            float v1 = (kg < DD) ? n0[(long)(b + 8) * DD + kg] : 0.f;
            n0s[kk][b]     = v0;
            n0s[kk][b + 8] = v1;
        }
        {   // W1 tile: 128h x 32k
            int kk = t & 31; int r0 = t >> 5;     // 0..7
            long kg = k0 + kk;
#pragma unroll
            for (int j = 0; j < 16; ++j) {
                int h = r0 + j * 8;
                ws[kk][h] = (kg < DD) ? W1[(long)(hblk + h) * DD + kg] : 0.f;
            }
        }
        __syncthreads();
#pragma unroll
        for (int kk = 0; kk < 32; ++kk) {
            float4 a = *(const float4*)&n0s[kk][by * 4];
            float2 w = *(const float2*)&ws[kk][hx * 2];
            acc[0][0] += a.x * w.x;  acc[0][1] += a.x * w.y;
            acc[1][0] += a.y * w.x;  acc[1][1] += a.y * w.y;
            acc[2][0] += a.z * w.x;  acc[2][1] += a.z * w.y;
            acc[3][0] += a.w * w.x;  acc[3][1] += a.w * w.y;
        }
        __syncthreads();
    }
#pragma unroll
    for (int bi = 0; bi < 4; ++bi)
#pragma unroll
        for (int hi = 0; hi < 2; ++hi)
            atomicAdd(&g1[(by * 4 + bi) * HH + hblk + hx * 2 + hi], acc[bi][hi]);
}

// ---------------- small kernels ----------------------------------------------
__global__ void init_g1_kernel(const float* __restrict__ b1, const float* __restrict__ n2,
                               const float* __restrict__ W2, float* __restrict__ g1)
{
    int b = blockIdx.x, h = threadIdx.x;
    g1[b * HH + h] = b1[h] + n2[b * NCC] * W2[h] + n2[b * NCC + 1] * W2[HH + h];
}

__global__ void g2_kernel(const float* __restrict__ n1, const float* __restrict__ W2,
                          const float* __restrict__ b2, float* __restrict__ n2n)
{
    int t = threadIdx.x;
    int wid = t >> 5, lane = t & 31;
    int b = wid >> 1, c = wid & 1;
    float s = 0.f;
    for (int h = lane; h < HH; h += 32)
        s += n1[b * HH + h] * W2[c * HH + h];
#pragma unroll
    for (int off = 16; off > 0; off >>= 1)
        s += __shfl_down_sync(0xffffffffu, s, off);
    if (lane == 0) n2n[b * NCC + c] = tanhf(b2[c] + s);
}

__global__ void tanh_n1_kernel(const float* __restrict__ g1, float* __restrict__ n1n)
{
    int i = blockIdx.x * blockDim.x + threadIdx.x;
    n1n[i] = tanhf(g1[i]);
}

// ---------------- row softmax over P (rows of length S) ----------------------
__global__ __launch_bounds__(256)
void softmax_kernel(float* __restrict__ P)
{
    __shared__ float red[256];
    float* p = P + (long)blockIdx.x * SS;
    int t = threadIdx.x;

    float mx = -INFINITY;
    for (int i = t; i < SS; i += 256) mx = fmaxf(mx, p[i]);
    red[t] = mx; __syncthreads();
    for (int s = 128; s > 0; s >>= 1) {
        if (t < s) red[t] = fmaxf(red[t], red[t + s]);
        __syncthreads();
    }
    mx = red[0]; __syncthreads();

    float sum = 0.f;
    for (int i = t; i < SS; i += 256) {
        float e = expf(p[i] - mx);
        p[i] = e;
        sum += e;
    }
    red[t] = sum; __syncthreads();
    for (int s = 128; s > 0; s >>= 1) {
        if (t < s) red[t] += red[t + s];
        __syncthreads();
    }
    float inv = 1.f / red[0]; __syncthreads();
    for (int i = t; i < SS; i += 256) p[i] *= inv;
}

// ---------------- host driver ------------------------------------------------
static float* sym_addr(const void* sym)
{
    void* p = nullptr;
    cudaGetSymbolAddress(&p, sym);
    return (float*)p;
}

extern "C" void kernel_launch(void* const* d_in, const int* in_sizes, int n_in,
                              void* d_out, int out_size)
{
    const float* x   = (const float*)d_in[0];
    // d_in[1] = y (unused, beta=0)
    const float* n0i = (const float*)d_in[2];
    const float* n1i = (const float*)d_in[3];
    const float* n2i = (const float*)d_in[4];
    const float* W0  = (const float*)d_in[5];
    const float* W1  = (const float*)d_in[6];
    const float* b1  = (const float*)d_in[7];
    const float* W2  = (const float*)d_in[8];
    const float* b2  = (const float*)d_in[9];
    float* out = (float*)d_out;

    float* Wx  = sym_addr(g_Wx);
    float* g0  = sym_addr(g_g0);
    float* P   = sym_addr(g_P);
    float* g1  = sym_addr(g_g1);
    float* n0buf[2] = { sym_addr(g_n0a), sym_addr(g_n0b) };
    float* n1buf[2] = { sym_addr(g_n1a), sym_addr(g_n1b) };
    float* n2buf[2] = { sym_addr(g_n2a), sym_addr(g_n2b) };

    const float scale = 1.0f / sqrtf((float)EE);

    // Wx = x(9600x300) @ W0^T  (constant across steps)
    {
        dim3 grid((EE + 63) / 64, (BB * SS + 63) / 64, 1);
        gemm_nt_kernel<<<grid, 256>>>(x, W0, Wx, BB * SS, EE, EE, 0, 0, 0, 1.0f);
    }

    const float* n0c = n0i;
    const float* n1c = n1i;
    const float* n2c = n2i;

    for (int step = 0; step < TT; ++step) {
        float* n0n = n0buf[step & 1];
        float* n1n = n1buf[step & 1];
        float* n2n = n2buf[step & 1];

        // g1 = b1 + n2c @ W2 ; n2n = tanh(b2 + n1c @ W2^T)
        init_g1_kernel<<<BB, HH>>>(b1, n2c, W2, g1);
        g2_kernel<<<1, 1024>>>(n1c, W2, b2, n2n);

        // g0 = Wx + n1c @ W1
        g0_kernel<<<(int)((DD / 2 + 255) / 256), 256>>>(n1c, W1, Wx, g0);

        // g1 += n0c_flat @ W1^T ; n1n = tanh(g1)
        {
            dim3 grid((unsigned)((DD + G1_KCHUNK - 1) / G1_KCHUNK), HH / 128);
            g1_kernel<<<grid, 256>>>(n0c, W1, g1);
        }
        tanh_n1_kernel<<<BB, HH>>>(g1, n1n);

        // scores = scale * g0 @ x^T  (batched)
        {
            dim3 grid((SS + 63) / 64, (SS + 63) / 64, BB);
            gemm_nt_kernel<<<grid, 256>>>(g0, x, P, SS, SS, EE, SE_, SE_, SSQ, scale);
        }
        softmax_kernel<<<BB * SS, 256>>>(P);
        // n0n = P @ x  (batched)
        {
            dim3 grid((EE + 63) / 64, (SS + 63) / 64, BB);
            gemm_nn_kernel<<<grid, 256>>>(P, x, n0n, SS, EE, SS, SSQ, SE_, SE_);
        }

        n0c = n0n; n1c = n1n; n2c = n2n;
    }

    // pack output: n0 | n1 | n2
    cudaMemcpyAsync(out, n0c, (size_t)BB * SS * EE * sizeof(float),
                    cudaMemcpyDeviceToDevice, 0);
    cudaMemcpyAsync(out + (long)BB * SS * EE, n1c, (size_t)BB * HH * sizeof(float),
                    cudaMemcpyDeviceToDevice, 0);
    cudaMemcpyAsync(out + (long)BB * SS * EE + BB * HH, n2c,
                    (size_t)BB * NCC * sizeof(float), cudaMemcpyDeviceToDevice, 0);
}

// round 2
// speedup vs baseline: 1.5093x; 1.5093x over previous
#include <cuda_runtime.h>
#include <math.h>

// Problem constants
#define BB   16
#define SS   600
#define EE   300
#define HH   512
#define NCC  2
#define DD   180000L          // S*E
#define SE_  180000L          // per-batch n0/x stride
#define SSQ  360000L          // S*S per-batch score stride
#define TT   3

// ---------------- scratch (device globals; no allocation allowed) -------------
__device__ float g_Wx[BB * SS * EE];       // 11.5 MB
__device__ float g_g0[BB * SS * EE];       // 11.5 MB
__device__ float g_P [BB * SS * SS];       // 23 MB
__device__ float g_n0a[BB * SS * EE];
__device__ float g_n0b[BB * SS * EE];
__device__ float g_n1a[BB * HH];
__device__ float g_n1b[BB * HH];
__device__ float g_n2a[BB * NCC];
__device__ float g_n2b[BB * NCC];
__device__ float g_g1 [BB * HH];

// ---------------- generic NT GEMM: C[m,n] = alpha * sum_k A[m,k]*B[n,k] ------
__global__ __launch_bounds__(256)
void gemm_nt_kernel(const float* __restrict__ A, const float* __restrict__ B,
                    float* __restrict__ C, int M, int N, int K,
                    long sA, long sB, long sC, float alpha)
{
    __shared__ float As[16][68];
    __shared__ float Bs[16][68];
    const float* Ab = A + (long)blockIdx.z * sA;
    const float* Bb = B + (long)blockIdx.z * sB;
    float*       Cb = C + (long)blockIdx.z * sC;
    int t  = threadIdx.x;
    int tx = t & 15, ty = t >> 4;
    int m0 = blockIdx.y * 64, n0 = blockIdx.x * 64;
    int lk = t & 15, lr = t >> 4;
    float acc[4][4] = {};

    for (int k0 = 0; k0 < K; k0 += 16) {
        int kg = k0 + lk;
        bool kin = (kg < K);
#pragma unroll
        for (int j = 0; j < 4; ++j) {
            int r = lr + j * 16;
            int m = m0 + r, n = n0 + r;
            As[lk][r] = (kin && m < M) ? Ab[(long)m * K + kg] : 0.f;
            Bs[lk][r] = (kin && n < N) ? Bb[(long)n * K + kg] : 0.f;
        }
        __syncthreads();
#pragma unroll
        for (int kk = 0; kk < 16; ++kk) {
            float4 av = *(const float4*)&As[kk][ty * 4];
            float4 bv = *(const float4*)&Bs[kk][tx * 4];
            float am[4] = {av.x, av.y, av.z, av.w};
            float bn[4] = {bv.x, bv.y, bv.z, bv.w};
#pragma unroll
            for (int i = 0; i < 4; ++i)
#pragma unroll
                for (int j = 0; j < 4; ++j)
                    acc[i][j] += am[i] * bn[j];
        }
        __syncthreads();
    }
    int n = n0 + tx * 4;
    if (n < N) {
#pragma unroll
        for (int i = 0; i < 4; ++i) {
            int m = m0 + ty * 4 + i;
            if (m < M) {
                float4 o = make_float4(acc[i][0] * alpha, acc[i][1] * alpha,
                                       acc[i][2] * alpha, acc[i][3] * alpha);
                *(float4*)&Cb[(long)m * N + n] = o;
            }
        }
    }
}

// ---------------- generic NN GEMM: C[m,n] = sum_k A[m,k]*B[k,n] --------------
__global__ __launch_bounds__(256)
void gemm_nn_kernel(const float* __restrict__ A, const float* __restrict__ B,
                    float* __restrict__ C, int M, int N, int K,
                    long sA, long sB, long sC)
{
    __shared__ float As[16][68];
    __shared__ float Bs[16][68];
    const float* Ab = A + (long)blockIdx.z * sA;
    const float* Bb = B + (long)blockIdx.z * sB;
    float*       Cb = C + (long)blockIdx.z * sC;
    int t  = threadIdx.x;
    int tx = t & 15, ty = t >> 4;
    int m0 = blockIdx.y * 64, n0 = blockIdx.x * 64;
    int lkA = t & 15, lrA = t >> 4;
    int lnB = t & 63, lkB = t >> 6;
    float acc[4][4] = {};

    for (int k0 = 0; k0 < K; k0 += 16) {
#pragma unroll
        for (int j = 0; j < 4; ++j) {
            int r = lrA + j * 16;
            int m = m0 + r;
            int kg = k0 + lkA;
            As[lkA][r] = (kg < K && m < M) ? Ab[(long)m * K + kg] : 0.f;
        }
#pragma unroll
        for (int j = 0; j < 4; ++j) {
            int kk = lkB + j * 4;
            int kg = k0 + kk;
            int n  = n0 + lnB;
            Bs[kk][lnB] = (kg < K && n < N) ? Bb[(long)kg * N + n] : 0.f;
        }
        __syncthreads();
#pragma unroll
        for (int kk = 0; kk < 16; ++kk) {
            float4 av = *(const float4*)&As[kk][ty * 4];
            float4 bv = *(const float4*)&Bs[kk][tx * 4];
            float am[4] = {av.x, av.y, av.z, av.w};
            float bn[4] = {bv.x, bv.y, bv.z, bv.w};
#pragma unroll
            for (int i = 0; i < 4; ++i)
#pragma unroll
                for (int j = 0; j < 4; ++j)
                    acc[i][j] += am[i] * bn[j];
        }
        __syncthreads();
    }
    int n = n0 + tx * 4;
    if (n < N) {
#pragma unroll
        for (int i = 0; i < 4; ++i) {
            int m = m0 + ty * 4 + i;
            if (m < M) {
                float4 o = make_float4(acc[i][0], acc[i][1], acc[i][2], acc[i][3]);
                *(float4*)&Cb[(long)m * N + n] = o;
            }
        }
    }
}

// ---------------- g0 = Wx + n1 @ W1 ------------------------------------------
// 8 batches x 4 d-columns per thread. blockIdx.x = dtile*2 + bgroup, so the two
// b-groups sharing a W1 d-tile are adjacent -> co-resident -> L2 reuse.
__global__ __launch_bounds__(256)
void g0_kernel(const float* __restrict__ n1, const float* __restrict__ W1,
               const float* __restrict__ Wx, float* __restrict__ g0)
{
    __shared__ float n1s[8 * HH];    // 16 KB (our batch group only)
    int bg = blockIdx.x & 1;
    int dt = blockIdx.x >> 1;
    int t  = threadIdx.x;
    const float* n1p = n1 + bg * 8 * HH;
    for (int i = t; i < 8 * HH; i += 256) n1s[i] = n1p[i];
    __syncthreads();

    long d = ((long)dt * 256 + t) * 4;
    if (d >= DD) return;

    float acc[8][4] = {};
    const float* wp = W1 + d;
#pragma unroll 4
    for (int h = 0; h < HH; ++h) {
        float4 w = *(const float4*)(wp + (long)h * DD);
#pragma unroll
        for (int b = 0; b < 8; ++b) {
            float v = n1s[b * HH + h];
            acc[b][0] += v * w.x;
            acc[b][1] += v * w.y;
            acc[b][2] += v * w.z;
            acc[b][3] += v * w.w;
        }
    }
#pragma unroll
    for (int b = 0; b < 8; ++b) {
        long o = (long)(bg * 8 + b) * DD + d;
        float4 wx = *(const float4*)(Wx + o);
        float4 r = make_float4(wx.x + acc[b][0], wx.y + acc[b][1],
                               wx.z + acc[b][2], wx.w + acc[b][3]);
        *(float4*)(g0 + o) = r;
    }
}

// ---------------- g1 += n0flat @ W1^T  (split-K, double-buffered) ------------
#define G1_KCHUNK 2048L
__global__ __launch_bounds__(256)
void g1_kernel(const float* __restrict__ n0, const float* __restrict__ W1,
               float* __restrict__ g1)
{
    __shared__ float n0s[32][20];     // [kk][b]
    __shared__ float ws [32][130];    // [kk][h]
    int t  = threadIdx.x;
    int hx = t & 63, by = t >> 6;     // micro: 4 b x 2 h
    int hblk = blockIdx.y * 128;
    long kstart = (long)blockIdx.x * G1_KCHUNK;
    long kend   = kstart + G1_KCHUNK; if (kend > DD) kend = DD;
    int kk = t & 31, br = t >> 5;     // loader coords (br 0..7)
    const float* wbase = W1 + (long)hblk * DD;

    float wr[16], nr0, nr1;

    // prologue: load first tile
    {
        long kg = kstart + kk;
        nr0 = n0[(long)br * DD + kg];
        nr1 = n0[(long)(br + 8) * DD + kg];
#pragma unroll
        for (int j = 0; j < 16; ++j)
            wr[j] = wbase[(long)(br + j * 8) * DD + kg];
        n0s[kk][br]     = nr0;
        n0s[kk][br + 8] = nr1;
#pragma unroll
        for (int j = 0; j < 16; ++j)
            ws[kk][br + j * 8] = wr[j];
    }
    __syncthreads();

    float acc[4][2] = {};
    for (long k0 = kstart; k0 < kend; k0 += 32) {
        long kn = k0 + 32;
        bool more = (kn < kend);
        if (more) {   // prefetch next tile into registers (overlaps compute)
            long kg = kn + kk;
            nr0 = n0[(long)br * DD + kg];
            nr1 = n0[(long)(br + 8) * DD + kg];
#pragma unroll
            for (int j = 0; j < 16; ++j)
                wr[j] = wbase[(long)(br + j * 8) * DD + kg];
        }
#pragma unroll
        for (int k2 = 0; k2 < 32; ++k2) {
            float4 a = *(const float4*)&n0s[k2][by * 4];
            float2 w = *(const float2*)&ws[k2][hx * 2];
            acc[0][0] += a.x * w.x;  acc[0][1] += a.x * w.y;
            acc[1][0] += a.y * w.x;  acc[1][1] += a.y * w.y;
            acc[2][0] += a.z * w.x;  acc[2][1] += a.z * w.y;
            acc[3][0] += a.w * w.x;  acc[3][1] += a.w * w.y;
        }
        __syncthreads();
        if (more) {
            n0s[kk][br]     = nr0;
            n0s[kk][br + 8] = nr1;
#pragma unroll
            for (int j = 0; j < 16; ++j)
                ws[kk][br + j * 8] = wr[j];
        }
        __syncthreads();
    }
#pragma unroll
    for (int bi = 0; bi < 4; ++bi)
#pragma unroll
        for (int hi = 0; hi < 2; ++hi)
            atomicAdd(&g1[(by * 4 + bi) * HH + hblk + hx * 2 + hi], acc[bi][hi]);
}

// ---------------- small kernels ----------------------------------------------
__global__ void init_g1_kernel(const float* __restrict__ b1, const float* __restrict__ n2,
                               const float* __restrict__ W2, float* __restrict__ g1)
{
    int b = blockIdx.x, h = threadIdx.x;
    g1[b * HH + h] = b1[h] + n2[b * NCC] * W2[h] + n2[b * NCC + 1] * W2[HH + h];
}

__global__ void g2_kernel(const float* __restrict__ n1, const float* __restrict__ W2,
                          const float* __restrict__ b2, float* __restrict__ n2n)
{
    int t = threadIdx.x;
    int wid = t >> 5, lane = t & 31;
    int b = wid >> 1, c = wid & 1;
    float s = 0.f;
    for (int h = lane; h < HH; h += 32)
        s += n1[b * HH + h] * W2[c * HH + h];
#pragma unroll
    for (int off = 16; off > 0; off >>= 1)
        s += __shfl_down_sync(0xffffffffu, s, off);
    if (lane == 0) n2n[b * NCC + c] = tanhf(b2[c] + s);
}

__global__ void tanh_n1_kernel(const float* __restrict__ g1, float* __restrict__ n1n)
{
    int i = blockIdx.x * blockDim.x + threadIdx.x;
    n1n[i] = tanhf(g1[i]);
}

// step 0: n0=n1=n2=0 structurally -> n1 = tanh(b1), n2 = tanh(b2)
__global__ void init_step0_kernel(const float* __restrict__ b1, const float* __restrict__ b2,
                                  float* __restrict__ n1n, float* __restrict__ n2n)
{
    int b = blockIdx.x, h = threadIdx.x;
    n1n[b * HH + h] = tanhf(b1[h]);
    if (h < NCC) n2n[b * NCC + h] = tanhf(b2[h]);
}

// ---------------- row softmax over P (rows of length S) ----------------------
__global__ __launch_bounds__(256)
void softmax_kernel(float* __restrict__ P)
{
    __shared__ float red[256];
    float* p = P + (long)blockIdx.x * SS;
    int t = threadIdx.x;

    float mx = -INFINITY;
    for (int i = t; i < SS; i += 256) mx = fmaxf(mx, p[i]);
    red[t] = mx; __syncthreads();
    for (int s = 128; s > 0; s >>= 1) {
        if (t < s) red[t] = fmaxf(red[t], red[t + s]);
        __syncthreads();
    }
    mx = red[0]; __syncthreads();

    float sum = 0.f;
    for (int i = t; i < SS; i += 256) {
        float e = expf(p[i] - mx);
        p[i] = e;
        sum += e;
    }
    red[t] = sum; __syncthreads();
    for (int s = 128; s > 0; s >>= 1) {
        if (t < s) red[t] += red[t + s];
        __syncthreads();
    }
    float inv = 1.f / red[0]; __syncthreads();
    for (int i = t; i < SS; i += 256) p[i] *= inv;
}

// ---------------- host driver ------------------------------------------------
static float* sym_addr(const void* sym)
{
    void* p = nullptr;
    cudaGetSymbolAddress(&p, sym);
    return (float*)p;
}

extern "C" void kernel_launch(void* const* d_in, const int* in_sizes, int n_in,
                              void* d_out, int out_size)
{
    const float* x   = (const float*)d_in[0];
    // d_in[1] = y (unused, beta = 0)
    const float* W0  = (const float*)d_in[5];
    const float* W1  = (const float*)d_in[6];
    const float* b1  = (const float*)d_in[7];
    const float* W2  = (const float*)d_in[8];
    const float* b2  = (const float*)d_in[9];
    float* out = (float*)d_out;

    float* Wx  = sym_addr(g_Wx);
    float* g0  = sym_addr(g_g0);
    float* P   = sym_addr(g_P);
    float* g1  = sym_addr(g_g1);
    float* n0buf[2] = { sym_addr(g_n0a), sym_addr(g_n0b) };
    float* n1buf[2] = { sym_addr(g_n1a), sym_addr(g_n1b) };
    float* n2buf[2] = { sym_addr(g_n2a), sym_addr(g_n2b) };

    const float scale = 1.0f / sqrtf((float)EE);

    // Wx = x(9600x300) @ W0^T  (constant across steps)
    {
        dim3 grid((EE + 63) / 64, (BB * SS + 63) / 64, 1);
        gemm_nt_kernel<<<grid, 256>>>(x, W0, Wx, BB * SS, EE, EE, 0, 0, 0, 1.0f);
    }

    // ---------------- step 0 (neurons are structurally zero) -----------------
    // g0 = Wx, g1 = b1, g2 = b2
    init_step0_kernel<<<BB, HH>>>(b1, b2, n1buf[0], n2buf[0]);
    {
        dim3 grid((SS + 63) / 64, (SS + 63) / 64, BB);
        gemm_nt_kernel<<<grid, 256>>>(Wx, x, P, SS, SS, EE, SE_, SE_, SSQ, scale);
    }
    softmax_kernel<<<BB * SS, 256>>>(P);
    {
        dim3 grid((EE + 63) / 64, (SS + 63) / 64, BB);
        gemm_nn_kernel<<<grid, 256>>>(P, x, n0buf[0], SS, EE, SS, SSQ, SE_, SE_);
    }

    const float* n0c = n0buf[0];
    const float* n1c = n1buf[0];
    const float* n2c = n2buf[0];

    // ---------------- steps 1..T-1 -------------------------------------------
    for (int step = 1; step < TT; ++step) {
        float* n0n = n0buf[step & 1];
        float* n1n = n1buf[step & 1];
        float* n2n = n2buf[step & 1];

        // g1 = b1 + n2c @ W2 ; n2n = tanh(b2 + n1c @ W2^T)
        init_g1_kernel<<<BB, HH>>>(b1, n2c, W2, g1);
        g2_kernel<<<1, 1024>>>(n1c, W2, b2, n2n);

        // g0 = Wx + n1c @ W1
        {
            int dtiles = (int)((DD / 4 + 255) / 256);   // 176
            g0_kernel<<<dtiles * 2, 256>>>(n1c, W1, Wx, g0);
        }

        // g1 += n0c_flat @ W1^T ; n1n = tanh(g1)
        {
            dim3 grid((unsigned)((DD + G1_KCHUNK - 1) / G1_KCHUNK), HH / 128);
            g1_kernel<<<grid, 256>>>(n0c, W1, g1);
        }
        tanh_n1_kernel<<<BB, HH>>>(g1, n1n);

        // scores = scale * g0 @ x^T  (batched)
        {
            dim3 grid((SS + 63) / 64, (SS + 63) / 64, BB);
            gemm_nt_kernel<<<grid, 256>>>(g0, x, P, SS, SS, EE, SE_, SE_, SSQ, scale);
        }
        softmax_kernel<<<BB * SS, 256>>>(P);
        // n0n = P @ x  (batched)
        {
            dim3 grid((EE + 63) / 64, (SS + 63) / 64, BB);
            gemm_nn_kernel<<<grid, 256>>>(P, x, n0n, SS, EE, SS, SSQ, SE_, SE_);
        }

        n0c = n0n; n1c = n1n; n2c = n2n;
    }

    // pack output: n0 | n1 | n2
    cudaMemcpyAsync(out, n0c, (size_t)BB * SS * EE * sizeof(float),
                    cudaMemcpyDeviceToDevice, 0);
    cudaMemcpyAsync(out + (long)BB * SS * EE, n1c, (size_t)BB * HH * sizeof(float),
                    cudaMemcpyDeviceToDevice, 0);
    cudaMemcpyAsync(out + (long)BB * SS * EE + BB * HH, n2c,
                    (size_t)BB * NCC * sizeof(float), cudaMemcpyDeviceToDevice, 0);
}

// round 4
// speedup vs baseline: 1.6774x; 1.1113x over previous
#include <cuda_runtime.h>
#include <cuda_bf16.h>
#include <math.h>
#include <stdint.h>

// Problem constants
#define BB   16
#define SS   600
#define EE   300
#define HH   512
#define NCC  2
#define DD   180000L
#define TT   3

// bf16 triple-K layout widths
#define KA3   960    // g0/x triple width (3 x 320)
#define KP3   1920   // P/xT triple width (3 x 640)

// ---------------- scratch (device globals) -----------------------------------
__device__ float g_Wx [BB * SS * EE];
__device__ float g_Praw[BB * SS * SS];
__device__ float g_n0a[BB * SS * EE];
__device__ float g_n0b[BB * SS * EE];
__device__ float g_n1a[BB * HH];
__device__ float g_n1b[BB * HH];
__device__ float g_n2a[BB * NCC];
__device__ float g_n2b[BB * NCC];
__device__ float g_g1 [BB * HH];
__device__ __nv_bfloat16 g_g03[(size_t)BB * SS * KA3];   // A scores: (hi|lo|hi)
__device__ __nv_bfloat16 g_x3 [(size_t)BB * SS * KA3];   // B scores: (hi|hi|lo)
__device__ __nv_bfloat16 g_P3 [(size_t)BB * SS * KP3];   // A PV:     (hi|lo|hi)
__device__ __nv_bfloat16 g_xT3[(size_t)BB * 320 * KP3];  // B PV:     (hi|hi|lo)

// ---------------- helpers -----------------------------------------------------
__device__ __forceinline__ uint32_t smem_u32(const void* p) {
    uint32_t a;
    asm("{ .reg .u64 t; cvta.to.shared.u64 t, %1; cvt.u32.u64 %0, t; }" : "=r"(a) : "l"(p));
    return a;
}
__device__ __forceinline__ void ldm_x4(uint32_t* r, uint32_t addr) {
    asm volatile("ldmatrix.sync.aligned.m8n8.x4.shared.b16 {%0,%1,%2,%3}, [%4];"
                 : "=r"(r[0]), "=r"(r[1]), "=r"(r[2]), "=r"(r[3]) : "r"(addr));
}
__device__ __forceinline__ void mma16816(float* c, const uint32_t* a, const uint32_t* b) {
    asm volatile(
        "mma.sync.aligned.m16n8k16.row.col.f32.bf16.bf16.f32 "
        "{%0,%1,%2,%3}, {%4,%5,%6,%7}, {%8,%9}, {%0,%1,%2,%3};"
        : "+f"(c[0]), "+f"(c[1]), "+f"(c[2]), "+f"(c[3])
        : "r"(a[0]), "r"(a[1]), "r"(a[2]), "r"(a[3]), "r"(b[0]), "r"(b[1]));
}
__device__ __forceinline__ void split_bf16(float v, __nv_bfloat16& hi, __nv_bfloat16& lo) {
    hi = __float2bfloat16(v);
    lo = __float2bfloat16(v - __bfloat162float(hi));
}

// ---------------- HMMA GEMM: C = A3 · B3^T (triple-K bf16, NT) ----------------
// 256 threads, block tile 128x128, K-tile 64. 8 warps: 2(m) x 4(n), warp 64x32.
__global__ __launch_bounds__(256)
void hmma_gemm_kernel(const __nv_bfloat16* __restrict__ A3,
                      const __nv_bfloat16* __restrict__ B3,
                      float* __restrict__ C,
                      int ldA, long bsA, int rowsA,
                      int ldB, long bsB, int rowsB,
                      int ldC, long bsC, int Mvalid, int Nvalid,
                      int kchunks)
{
    __shared__ __nv_bfloat16 As[128][72];
    __shared__ __nv_bfloat16 Bs[128][72];
    const int t = threadIdx.x, lane = t & 31, wid = t >> 5;
    const int wm = wid >> 2, wn = wid & 3;
    const int b = blockIdx.z, m0 = blockIdx.y * 128, n0 = blockIdx.x * 128;
    const __nv_bfloat16* Ab = A3 + (long)b * bsA;
    const __nv_bfloat16* Bb = B3 + (long)b * bsB;
    float acc[4][4][4] = {};
    const uint4 zz = make_uint4(0, 0, 0, 0);

    const int a_lm = lane & 15;               // A: row-in-16
    const int a_lk = (lane >> 4) * 8;         // A: k-half
    const int b_ln = (lane & 7) + ((lane >> 4) & 1) * 8;   // B: n row
    const int b_lk = ((lane >> 3) & 1) * 8;                // B: k-half

    for (int ch = 0; ch < kchunks; ++ch) {
        const long kg = (long)ch * 64;
#pragma unroll
        for (int i = 0; i < 4; ++i) {
            int idx = t + i * 256;            // 0..1023
            int row = idx >> 3, q = idx & 7;
            const uint4* pa = (const uint4*)(Ab + (long)(m0 + row) * ldA + kg + q * 8);
            const uint4* pb = (const uint4*)(Bb + (long)(n0 + row) * ldB + kg + q * 8);
            *(uint4*)&As[row][q * 8] = (m0 + row < rowsA) ? *pa : zz;
            *(uint4*)&Bs[row][q * 8] = (n0 + row < rowsB) ? *pb : zz;
        }
        __syncthreads();
#pragma unroll
        for (int ks = 0; ks < 4; ++ks) {
            uint32_t af[4][4], bf[4][2];
#pragma unroll
            for (int mf = 0; mf < 4; ++mf)
                ldm_x4(af[mf], smem_u32(&As[wm * 64 + mf * 16 + a_lm][ks * 16 + a_lk]));
#pragma unroll
            for (int nf2 = 0; nf2 < 2; ++nf2) {
                uint32_t r[4];
                ldm_x4(r, smem_u32(&Bs[wn * 32 + nf2 * 16 + b_ln][ks * 16 + b_lk]));
                bf[nf2 * 2][0] = r[0];     bf[nf2 * 2][1] = r[1];
                bf[nf2 * 2 + 1][0] = r[2]; bf[nf2 * 2 + 1][1] = r[3];
            }
#pragma unroll
            for (int mf = 0; mf < 4; ++mf)
#pragma unroll
                for (int nf = 0; nf < 4; ++nf)
                    mma16816(acc[mf][nf], af[mf], bf[nf]);
        }
        __syncthreads();
    }

    // epilogue: acc regs {c0,c1} -> (m, n..n+1), {c2,c3} -> (m+8, n..n+1)
    float* Cb = C + (long)b * bsC;
    const int mbase = m0 + wm * 64, nbase = n0 + wn * 32;
#pragma unroll
    for (int mf = 0; mf < 4; ++mf) {
#pragma unroll
        for (int nf = 0; nf < 4; ++nf) {
            int m = mbase + mf * 16 + (lane >> 2);
            int n = nbase + nf * 8 + (lane & 3) * 2;
            if (n < Nvalid) {
                if (m < Mvalid)
                    *(float2*)&Cb[(long)m * ldC + n] =
                        make_float2(acc[mf][nf][0], acc[mf][nf][1]);
                if (m + 8 < Mvalid)
                    *(float2*)&Cb[(long)(m + 8) * ldC + n] =
                        make_float2(acc[mf][nf][2], acc[mf][nf][3]);
            }
        }
    }
}

// ---------------- Wx GEMM (SIMT NT): C[m,n] = sum_k A[m,k]*B[n,k] ------------
__global__ __launch_bounds__(256)
void gemm_nt_kernel(const float* __restrict__ A, const float* __restrict__ B,
                    float* __restrict__ C, int M, int N, int K)
{
    __shared__ float As[16][68];
    __shared__ float Bs[16][68];
    int t  = threadIdx.x;
    int tx = t & 15, ty = t >> 4;
    int m0 = blockIdx.y * 64, n0 = blockIdx.x * 64;
    int lk = t & 15, lr = t >> 4;
    float acc[4][4] = {};

    for (int k0 = 0; k0 < K; k0 += 16) {
        int kg = k0 + lk;
        bool kin = (kg < K);
#pragma unroll
        for (int j = 0; j < 4; ++j) {
            int r = lr + j * 16;
            int m = m0 + r, n = n0 + r;
            As[lk][r] = (kin && m < M) ? A[(long)m * K + kg] : 0.f;
            Bs[lk][r] = (kin && n < N) ? B[(long)n * K + kg] : 0.f;
        }
        __syncthreads();
#pragma unroll
        for (int kk = 0; kk < 16; ++kk) {
            float4 av = *(const float4*)&As[kk][ty * 4];
            float4 bv = *(const float4*)&Bs[kk][tx * 4];
            float am[4] = {av.x, av.y, av.z, av.w};
            float bn[4] = {bv.x, bv.y, bv.z, bv.w};
#pragma unroll
            for (int i = 0; i < 4; ++i)
#pragma unroll
                for (int j = 0; j < 4; ++j)
                    acc[i][j] += am[i] * bn[j];
        }
        __syncthreads();
    }
    int n = n0 + tx * 4;
    if (n < N) {
#pragma unroll
        for (int i = 0; i < 4; ++i) {
            int m = m0 + ty * 4 + i;
            if (m < M)
                *(float4*)&C[(long)m * N + n] =
                    make_float4(acc[i][0], acc[i][1], acc[i][2], acc[i][3]);
        }
    }
}

// ---------------- g0 = Wx + n1 @ W1 -> scaled bf16 triple --------------------
// 8 batches x 2 cols per thread (low regs -> high occupancy / MLP).
__global__ __launch_bounds__(256)
void g0_kernel(const float* __restrict__ n1, const float* __restrict__ W1,
               const float* __restrict__ Wx, __nv_bfloat16* __restrict__ g03,
               float scale)
{
    __shared__ float n1s[8 * HH];
    int bg = blockIdx.x & 1;
    int dt = blockIdx.x >> 1;
    int t  = threadIdx.x;
    const float* n1p = n1 + bg * 8 * HH;
    for (int i = t; i < 8 * HH; i += 256) n1s[i] = n1p[i];
    __syncthreads();

    long d = ((long)dt * 256 + t) * 2;
    if (d >= DD) return;

    float acc[8][2] = {};
    const float* wp = W1 + d;
#pragma unroll 8
    for (int h = 0; h < HH; ++h) {
        float2 w = *(const float2*)(wp + (long)h * DD);
#pragma unroll
        for (int b = 0; b < 8; ++b) {
            float v = n1s[b * HH + h];
            acc[b][0] += v * w.x;
            acc[b][1] += v * w.y;
        }
    }
    int s = (int)(d / EE);
    int e = (int)(d % EE);
#pragma unroll
    for (int b = 0; b < 8; ++b) {
        long o = (long)(bg * 8 + b) * DD + d;
        float2 wx = *(const float2*)(Wx + o);
        float v0 = (wx.x + acc[b][0]) * scale;
        float v1 = (wx.y + acc[b][1]) * scale;
        __nv_bfloat16 hi[2], lo[2];
        split_bf16(v0, hi[0], lo[0]);
        split_bf16(v1, hi[1], lo[1]);
        long row = (long)(bg * 8 + b) * SS + s;
        __nv_bfloat16* out = g03 + row * KA3;
        *(uint32_t*)&out[e]       = *(uint32_t*)hi;   // sec0: hi
        *(uint32_t*)&out[320 + e] = *(uint32_t*)lo;   // sec1: lo
        *(uint32_t*)&out[640 + e] = *(uint32_t*)hi;   // sec2: hi
    }
}

// ---------------- g1 += n0flat @ W1^T  (split-K, double-buffered) ------------
#define G1_KCHUNK 2048L
__global__ __launch_bounds__(256)
void g1_kernel(const float* __restrict__ n0, const float* __restrict__ W1,
               float* __restrict__ g1)
{
    __shared__ float n0s[32][20];
    __shared__ float ws [32][130];
    int t  = threadIdx.x;
    int hx = t & 63, by = t >> 6;
    int hblk = blockIdx.y * 128;
    long kstart = (long)blockIdx.x * G1_KCHUNK;
    long kend   = kstart + G1_KCHUNK; if (kend > DD) kend = DD;
    int kk = t & 31, br = t >> 5;
    const float* wbase = W1 + (long)hblk * DD;

    float wr[16], nr0, nr1;
    {
        long kg = kstart + kk;
        nr0 = n0[(long)br * DD + kg];
        nr1 = n0[(long)(br + 8) * DD + kg];
#pragma unroll
        for (int j = 0; j < 16; ++j)
            wr[j] = wbase[(long)(br + j * 8) * DD + kg];
        n0s[kk][br]     = nr0;
        n0s[kk][br + 8] = nr1;
#pragma unroll
        for (int j = 0; j < 16; ++j)
            ws[kk][br + j * 8] = wr[j];
    }
    __syncthreads();

    float acc[4][2] = {};
    for (long k0 = kstart; k0 < kend; k0 += 32) {
        long kn = k0 + 32;
        bool more = (kn < kend);
        if (more) {
            long kg = kn + kk;
            nr0 = n0[(long)br * DD + kg];
            nr1 = n0[(long)(br + 8) * DD + kg];
#pragma unroll
            for (int j = 0; j < 16; ++j)
                wr[j] = wbase[(long)(br + j * 8) * DD + kg];
        }
#pragma unroll
        for (int k2 = 0; k2 < 32; ++k2) {
            float4 a = *(const float4*)&n0s[k2][by * 4];
            float2 w = *(const float2*)&ws[k2][hx * 2];
            acc[0][0] += a.x * w.x;  acc[0][1] += a.x * w.y;
            acc[1][0] += a.y * w.x;  acc[1][1] += a.y * w.y;
            acc[2][0] += a.z * w.x;  acc[2][1] += a.z * w.y;
            acc[3][0] += a.w * w.x;  acc[3][1] += a.w * w.y;
        }
        __syncthreads();
        if (more) {
            n0s[kk][br]     = nr0;
            n0s[kk][br + 8] = nr1;
#pragma unroll
            for (int j = 0; j < 16; ++j)
                ws[kk][br + j * 8] = wr[j];
        }
        __syncthreads();
    }
#pragma unroll
    for (int bi = 0; bi < 4; ++bi)
#pragma unroll
        for (int hi = 0; hi < 2; ++hi)
            atomicAdd(&g1[(by * 4 + bi) * HH + hblk + hx * 2 + hi], acc[bi][hi]);
}

// ---------------- small kernels ----------------------------------------------
__global__ void init_g1_kernel(const float* __restrict__ b1, const float* __restrict__ n2,
                               const float* __restrict__ W2, float* __restrict__ g1)
{
    int b = blockIdx.x, h = threadIdx.x;
    g1[b * HH + h] = b1[h] + n2[b * NCC] * W2[h] + n2[b * NCC + 1] * W2[HH + h];
}

__global__ void g2_kernel(const float* __restrict__ n1, const float* __restrict__ W2,
                          const float* __restrict__ b2, float* __restrict__ n2n)
{
    int t = threadIdx.x;
    int wid = t >> 5, lane = t & 31;
    int b = wid >> 1, c = wid & 1;
    float s = 0.f;
    for (int h = lane; h < HH; h += 32)
        s += n1[b * HH + h] * W2[c * HH + h];
#pragma unroll
    for (int off = 16; off > 0; off >>= 1)
        s += __shfl_down_sync(0xffffffffu, s, off);
    if (lane == 0) n2n[b * NCC + c] = tanhf(b2[c] + s);
}

__global__ void tanh_n1_kernel(const float* __restrict__ g1, float* __restrict__ n1n)
{
    int i = blockIdx.x * blockDim.x + threadIdx.x;
    n1n[i] = tanhf(g1[i]);
}

__global__ void init_step0_kernel(const float* __restrict__ b1, const float* __restrict__ b2,
                                  float* __restrict__ n1n, float* __restrict__ n2n)
{
    int b = blockIdx.x, h = threadIdx.x;
    n1n[b * HH + h] = tanhf(b1[h]);
    if (h < NCC) n2n[b * NCC + h] = tanhf(b2[h]);
}

// ---------------- x -> x3 (hi|hi|lo) and xT3 (hi|hi|lo) ----------------------
__global__ void conv_x_kernel(const float* __restrict__ x,
                              __nv_bfloat16* __restrict__ x3,
                              __nv_bfloat16* __restrict__ xT3)
{
    int s = blockIdx.x, b = blockIdx.y, e = threadIdx.x;
    __nv_bfloat16 zero = __float2bfloat16(0.f);
    if (s < SS) {
        float v = (e < EE) ? x[((long)b * SS + s) * EE + e] : 0.f;
        __nv_bfloat16 hi, lo;
        split_bf16(v, hi, lo);
        __nv_bfloat16* xr = x3 + ((long)b * SS + s) * KA3;
        xr[e] = hi; xr[320 + e] = hi; xr[640 + e] = lo;
        __nv_bfloat16* tr = xT3 + ((long)b * 320 + e) * KP3;
        tr[s] = hi; tr[640 + s] = hi; tr[1280 + s] = lo;
    } else {
        __nv_bfloat16* tr = xT3 + ((long)b * 320 + e) * KP3;
        tr[s] = zero; tr[640 + s] = zero; tr[1280 + s] = zero;
    }
}

// ---------------- step0: Wx -> scaled g0 triple ------------------------------
__global__ void conv_wx_kernel(const float* __restrict__ Wx,
                               __nv_bfloat16* __restrict__ g03, float scale)
{
    long r = blockIdx.x;
    int e = threadIdx.x;
    float v = (e < EE) ? scale * Wx[r * EE + e] : 0.f;
    __nv_bfloat16 hi, lo;
    split_bf16(v, hi, lo);
    __nv_bfloat16* out = g03 + r * KA3;
    out[e] = hi; out[320 + e] = lo; out[640 + e] = hi;
}

// ---------------- softmax + convert to P3 triple (hi|lo|hi) ------------------
__global__ __launch_bounds__(256)
void softmax_conv_kernel(const float* __restrict__ Praw, __nv_bfloat16* __restrict__ P3)
{
    __shared__ float red[256];
    long r = blockIdx.x;
    const float* p = Praw + r * SS;
    __nv_bfloat16* out = P3 + r * KP3;
    int t = threadIdx.x;

    float a0 = (t < SS)       ? p[t]       : -INFINITY;
    float a1 = (t + 256 < SS) ? p[t + 256] : -INFINITY;
    float a2 = (t + 512 < SS) ? p[t + 512] : -INFINITY;

    float mx = fmaxf(a0, fmaxf(a1, a2));
    red[t] = mx; __syncthreads();
    for (int s = 128; s > 0; s >>= 1) {
        if (t < s) red[t] = fmaxf(red[t], red[t + s]);
        __syncthreads();
    }
    mx = red[0]; __syncthreads();

    float e0 = (t < SS)       ? expf(a0 - mx) : 0.f;
    float e1 = (t + 256 < SS) ? expf(a1 - mx) : 0.f;
    float e2 = (t + 512 < SS) ? expf(a2 - mx) : 0.f;
    red[t] = e0 + e1 + e2; __syncthreads();
    for (int s = 128; s > 0; s >>= 1) {
        if (t < s) red[t] += red[t + s];
        __syncthreads();
    }
    float inv = 1.f / red[0];

    __nv_bfloat16 zero = __float2bfloat16(0.f);
    for (int k = 0; k < 3; ++k) {
        int i = t + k * 256;
        if (i >= 640) break;
        if (i < SS) {
            float v = (k == 0 ? e0 : (k == 1 ? e1 : e2)) * inv;
            __nv_bfloat16 hi, lo;
            split_bf16(v, hi, lo);
            out[i] = hi; out[640 + i] = lo; out[1280 + i] = hi;
        } else {
            out[i] = zero; out[640 + i] = zero; out[1280 + i] = zero;
        }
    }
}

// ---------------- host driver ------------------------------------------------
static float* sym_addr_f(const void* sym)
{
    void* p = nullptr;
    cudaGetSymbolAddress(&p, sym);
    return (float*)p;
}
static __nv_bfloat16* sym_addr_b(const void* sym)
{
    void* p = nullptr;
    cudaGetSymbolAddress(&p, sym);
    return (__nv_bfloat16*)p;
}

extern "C" void kernel_launch(void* const* d_in, const int* in_sizes, int n_in,
                              void* d_out, int out_size)
{
    const float* x   = (const float*)d_in[0];
    const float* W0  = (const float*)d_in[5];
    const float* W1  = (const float*)d_in[6];
    const float* b1  = (const float*)d_in[7];
    const float* W2  = (const float*)d_in[8];
    const float* b2  = (const float*)d_in[9];
    float* out = (float*)d_out;

    float* Wx   = sym_addr_f(g_Wx);
    float* Praw = sym_addr_f(g_Praw);
    float* g1   = sym_addr_f(g_g1);
    float* n0buf[2] = { sym_addr_f(g_n0a), sym_addr_f(g_n0b) };
    float* n1buf[2] = { sym_addr_f(g_n1a), sym_addr_f(g_n1b) };
    float* n2buf[2] = { sym_addr_f(g_n2a), sym_addr_f(g_n2b) };
    __nv_bfloat16* g03 = sym_addr_b(g_g03);
    __nv_bfloat16* x3  = sym_addr_b(g_x3);
    __nv_bfloat16* P3  = sym_addr_b(g_P3);
    __nv_bfloat16* xT3 = sym_addr_b(g_xT3);

    const float scale = 1.0f / sqrtf((float)EE);

    // one-time conversions + Wx GEMM
    {
        dim3 g(640, BB);
        conv_x_kernel<<<g, 320>>>(x, x3, xT3);
    }
    {
        dim3 grid((EE + 63) / 64, (BB * SS + 63) / 64);
        gemm_nt_kernel<<<grid, 256>>>(x, W0, Wx, BB * SS, EE, EE);
    }

    const float* n0c = nullptr;
    const float* n1c = nullptr;
    const float* n2c = nullptr;

    for (int step = 0; step < TT; ++step) {
        float* n0n = n0buf[step & 1];
        float* n1n = n1buf[step & 1];
        float* n2n = n2buf[step & 1];

        if (step == 0) {
            // neurons structurally zero: g0 = Wx, n1 = tanh(b1), n2 = tanh(b2)
            init_step0_kernel<<<BB, HH>>>(b1, b2, n1n, n2n);
            conv_wx_kernel<<<BB * SS, 320>>>(Wx, g03, scale);
        } else {
            init_g1_kernel<<<BB, HH>>>(b1, n2c, W2, g1);
            g2_kernel<<<1, 1024>>>(n1c, W2, b2, n2n);
            {
                int dtiles = (int)((DD / 2 + 255) / 256);   // 352
                g0_kernel<<<dtiles * 2, 256>>>(n1c, W1, Wx, g03, scale);
            }
            {
                dim3 grid((unsigned)((DD + G1_KCHUNK - 1) / G1_KCHUNK), HH / 128);
                g1_kernel<<<grid, 256>>>(n0c, W1, g1);
            }
            tanh_n1_kernel<<<BB, HH>>>(g1, n1n);
        }

        // scores = (scale*g0) @ x^T   [HMMA, triple-K bf16]
        {
            dim3 grid(5, 5, BB);
            hmma_gemm_kernel<<<grid, 256>>>(
                g03, x3, Praw,
                KA3, (long)SS * KA3, SS,
                KA3, (long)SS * KA3, SS,
                SS, (long)SS * SS, SS, SS,
                15);
        }
        softmax_conv_kernel<<<BB * SS, 256>>>(Praw, P3);
        // n0n = P @ x   [HMMA]
        {
            dim3 grid(3, 5, BB);
            hmma_gemm_kernel<<<grid, 256>>>(
                P3, xT3, n0n,
                KP3, (long)SS * KP3, SS,
                KP3, (long)320 * KP3, 320,
                EE, (long)SS * EE, SS, EE,
                30);
        }

        n0c = n0n; n1c = n1n; n2c = n2n;
    }

    // pack output: n0 | n1 | n2
    cudaMemcpyAsync(out, n0c, (size_t)BB * SS * EE * sizeof(float),
                    cudaMemcpyDeviceToDevice, 0);
    cudaMemcpyAsync(out + (long)BB * SS * EE, n1c, (size_t)BB * HH * sizeof(float),
                    cudaMemcpyDeviceToDevice, 0);
    cudaMemcpyAsync(out + (long)BB * SS * EE + BB * HH, n2c,
                    (size_t)BB * NCC * sizeof(float), cudaMemcpyDeviceToDevice, 0);
}

// round 5
// speedup vs baseline: 1.6931x; 1.0094x over previous
#include <cuda_runtime.h>
#include <cuda_bf16.h>
#include <math.h>
#include <stdint.h>

// Problem constants
#define BB   16
#define SS   600
#define EE   300
#define HH   512
#define NCC  2
#define DD   180000L
#define TT   3

// bf16 triple-K layout widths
#define KA3   960    // K=300-class triple (3 x 320)
#define KP3   1920   // K=600-class triple (3 x 640)

// ---------------- scratch (device globals) -----------------------------------
__device__ float g_Wx [BB * SS * EE];
__device__ float g_Praw[BB * SS * SS];
__device__ float g_n0a[BB * SS * EE];
__device__ float g_n0b[BB * SS * EE];
__device__ float g_n1a[BB * HH];
__device__ float g_n1b[BB * HH];
__device__ float g_n2a[BB * NCC];
__device__ float g_n2b[BB * NCC];
__device__ float g_g1 [BB * HH];
__device__ __nv_bfloat16 g_g03[(size_t)BB * SS * KA3];   // A scores: (hi|lo|hi)
__device__ __nv_bfloat16 g_x3 [(size_t)BB * SS * KA3];   // B scores: (hi|hi|lo)
__device__ __nv_bfloat16 g_P3 [(size_t)BB * SS * KP3];   // A PV:     (hi|lo|hi)
__device__ __nv_bfloat16 g_xT3[(size_t)BB * 320 * KP3];  // B PV:     (hi|hi|lo)
__device__ __nv_bfloat16 g_xA3[(size_t)BB * SS * KA3];   // A Wx:     (hi|lo|hi)
__device__ __nv_bfloat16 g_W03[(size_t)EE * KA3];        // B Wx:     (hi|hi|lo)
__device__ __nv_bfloat16 g_W1hi[(size_t)HH * DD];        // 184 MB
__device__ __nv_bfloat16 g_W1lo[(size_t)HH * DD];        // 184 MB
__device__ __nv_bfloat16 g_n0hi[(size_t)BB * DD];
__device__ __nv_bfloat16 g_n0lo[(size_t)BB * DD];
__device__ __nv_bfloat16 g_n1hi[BB * HH];
__device__ __nv_bfloat16 g_n1lo[BB * HH];

// ---------------- helpers -----------------------------------------------------
__device__ __forceinline__ uint32_t smem_u32(const void* p) {
    uint32_t a;
    asm("{ .reg .u64 t; cvta.to.shared.u64 t, %1; cvt.u32.u64 %0, t; }" : "=r"(a) : "l"(p));
    return a;
}
__device__ __forceinline__ void ldm_x4(uint32_t* r, uint32_t addr) {
    asm volatile("ldmatrix.sync.aligned.m8n8.x4.shared.b16 {%0,%1,%2,%3}, [%4];"
                 : "=r"(r[0]), "=r"(r[1]), "=r"(r[2]), "=r"(r[3]) : "r"(addr));
}
__device__ __forceinline__ void ldm_x4_t(uint32_t* r, uint32_t addr) {
    asm volatile("ldmatrix.sync.aligned.m8n8.x4.trans.shared.b16 {%0,%1,%2,%3}, [%4];"
                 : "=r"(r[0]), "=r"(r[1]), "=r"(r[2]), "=r"(r[3]) : "r"(addr));
}
__device__ __forceinline__ void mma16816(float* c, const uint32_t* a, const uint32_t* b) {
    asm volatile(
        "mma.sync.aligned.m16n8k16.row.col.f32.bf16.bf16.f32 "
        "{%0,%1,%2,%3}, {%4,%5,%6,%7}, {%8,%9}, {%0,%1,%2,%3};"
        : "+f"(c[0]), "+f"(c[1]), "+f"(c[2]), "+f"(c[3])
        : "r"(a[0]), "r"(a[1]), "r"(a[2]), "r"(a[3]), "r"(b[0]), "r"(b[1]));
}
__device__ __forceinline__ void split_bf16(float v, __nv_bfloat16& hi, __nv_bfloat16& lo) {
    hi = __float2bfloat16(v);
    lo = __float2bfloat16(v - __bfloat162float(hi));
}

// ---------------- generic HMMA GEMM: C = A3 · B3^T (triple-K bf16, NT) -------
// 256 threads, block tile 128x128, K-tile 64. 8 warps: 2(m) x 4(n), warp 64x32.
// Optional bf16 hi/lo outputs (same indexing as C).
__global__ __launch_bounds__(256)
void hmma_gemm_kernel(const __nv_bfloat16* __restrict__ A3,
                      const __nv_bfloat16* __restrict__ B3,
                      float* __restrict__ C,
                      __nv_bfloat16* __restrict__ Chi,
                      __nv_bfloat16* __restrict__ Clo,
                      int ldA, long bsA, int rowsA,
                      int ldB, long bsB, int rowsB,
                      int ldC, long bsC, int Mvalid, int Nvalid,
                      int kchunks)
{
    __shared__ __nv_bfloat16 As[128][72];
    __shared__ __nv_bfloat16 Bs[128][72];
    const int t = threadIdx.x, lane = t & 31, wid = t >> 5;
    const int wm = wid >> 2, wn = wid & 3;
    const int b = blockIdx.z, m0 = blockIdx.y * 128, n0 = blockIdx.x * 128;
    const __nv_bfloat16* Ab = A3 + (long)b * bsA;
    const __nv_bfloat16* Bb = B3 + (long)b * bsB;
    float acc[4][4][4] = {};
    const uint4 zz = make_uint4(0, 0, 0, 0);

    const int a_lm = lane & 15;
    const int a_lk = (lane >> 4) * 8;
    const int b_ln = (lane & 7) + ((lane >> 4) & 1) * 8;
    const int b_lk = ((lane >> 3) & 1) * 8;

    for (int ch = 0; ch < kchunks; ++ch) {
        const long kg = (long)ch * 64;
#pragma unroll
        for (int i = 0; i < 4; ++i) {
            int idx = t + i * 256;
            int row = idx >> 3, q = idx & 7;
            const uint4* pa = (const uint4*)(Ab + (long)(m0 + row) * ldA + kg + q * 8);
            const uint4* pb = (const uint4*)(Bb + (long)(n0 + row) * ldB + kg + q * 8);
            *(uint4*)&As[row][q * 8] = (m0 + row < rowsA) ? *pa : zz;
            *(uint4*)&Bs[row][q * 8] = (n0 + row < rowsB) ? *pb : zz;
        }
        __syncthreads();
#pragma unroll
        for (int ks = 0; ks < 4; ++ks) {
            uint32_t af[4][4], bf[4][2];
#pragma unroll
            for (int mf = 0; mf < 4; ++mf)
                ldm_x4(af[mf], smem_u32(&As[wm * 64 + mf * 16 + a_lm][ks * 16 + a_lk]));
#pragma unroll
            for (int nf2 = 0; nf2 < 2; ++nf2) {
                uint32_t r[4];
                ldm_x4(r, smem_u32(&Bs[wn * 32 + nf2 * 16 + b_ln][ks * 16 + b_lk]));
                bf[nf2 * 2][0] = r[0];     bf[nf2 * 2][1] = r[1];
                bf[nf2 * 2 + 1][0] = r[2]; bf[nf2 * 2 + 1][1] = r[3];
            }
#pragma unroll
            for (int mf = 0; mf < 4; ++mf)
#pragma unroll
                for (int nf = 0; nf < 4; ++nf)
                    mma16816(acc[mf][nf], af[mf], bf[nf]);
        }
        __syncthreads();
    }

    float* Cb = C + (long)b * bsC;
    const int mbase = m0 + wm * 64, nbase = n0 + wn * 32;
#pragma unroll
    for (int mf = 0; mf < 4; ++mf) {
#pragma unroll
        for (int nf = 0; nf < 4; ++nf) {
            int m = mbase + mf * 16 + (lane >> 2);
            int n = nbase + nf * 8 + (lane & 3) * 2;
            if (n < Nvalid) {
#pragma unroll
                for (int half = 0; half < 2; ++half) {
                    int mm = m + half * 8;
                    float v0 = acc[mf][nf][half * 2], v1 = acc[mf][nf][half * 2 + 1];
                    if (mm < Mvalid) {
                        long o = (long)mm * ldC + n;
                        *(float2*)&Cb[o] = make_float2(v0, v1);
                        if (Chi) {
                            __nv_bfloat16 h0, l0, h1, l1;
                            split_bf16(v0, h0, l0);
                            split_bf16(v1, h1, l1);
                            __nv_bfloat162 hh; hh.x = h0; hh.y = h1;
                            __nv_bfloat162 ll; ll.x = l0; ll.y = l1;
                            *(__nv_bfloat162*)&Chi[(long)b * bsC + o] = hh;
                            *(__nv_bfloat162*)&Clo[(long)b * bsC + o] = ll;
                        }
                    }
                }
            }
        }
    }
}

// ---------------- g0 = (Wx + n1 @ W1) * scale -> g03 triple (HMMA) ----------
// M=16 (batch), N = 256 d-cols per block, K = 512 (h). W1 consumed via trans-ldmatrix.
__global__ __launch_bounds__(256)
void g0_hmma_kernel(const __nv_bfloat16* __restrict__ n1hi,
                    const __nv_bfloat16* __restrict__ n1lo,
                    const __nv_bfloat16* __restrict__ W1hi,
                    const __nv_bfloat16* __restrict__ W1lo,
                    const float* __restrict__ Wx,
                    __nv_bfloat16* __restrict__ g03, float scale)
{
    __shared__ __nv_bfloat16 Bh[16][264];
    __shared__ __nv_bfloat16 Bl[16][264];
    const int t = threadIdx.x, lane = t & 31, wid = t >> 5;
    const long d0 = (long)blockIdx.x * 256;
    const int ar = lane >> 2, ac = (lane & 3) * 2;
    const int tr_r = lane & 15, tr_c = (lane >> 4) * 8;
    float acc[4][4] = {};
    const uint4 zz = make_uint4(0, 0, 0, 0);

    for (int kt = 0; kt < 32; ++kt) {
        const int kg = kt * 16;
#pragma unroll
        for (int i = 0; i < 2; ++i) {
            int task = t + i * 256;
            int row = task >> 5, seg = task & 31;
            long d = d0 + seg * 8;
            long off = (long)(kg + row) * DD + d;
            bool v = (d + 8 <= DD);
            *(uint4*)&Bh[row][seg * 8] = v ? *(const uint4*)(W1hi + off) : zz;
            *(uint4*)&Bl[row][seg * 8] = v ? *(const uint4*)(W1lo + off) : zz;
        }
        __syncthreads();
        uint32_t ah[4], al[4];
        ah[0] = *(const uint32_t*)(n1hi + ar * HH + kg + ac);
        ah[1] = *(const uint32_t*)(n1hi + (ar + 8) * HH + kg + ac);
        ah[2] = *(const uint32_t*)(n1hi + ar * HH + kg + ac + 8);
        ah[3] = *(const uint32_t*)(n1hi + (ar + 8) * HH + kg + ac + 8);
        al[0] = *(const uint32_t*)(n1lo + ar * HH + kg + ac);
        al[1] = *(const uint32_t*)(n1lo + (ar + 8) * HH + kg + ac);
        al[2] = *(const uint32_t*)(n1lo + ar * HH + kg + ac + 8);
        al[3] = *(const uint32_t*)(n1lo + (ar + 8) * HH + kg + ac + 8);

        uint32_t bh[4][2], bl[4][2];
#pragma unroll
        for (int nf2 = 0; nf2 < 2; ++nf2) {
            uint32_t r[4];
            ldm_x4_t(r, smem_u32(&Bh[tr_r][wid * 32 + nf2 * 16 + tr_c]));
            bh[nf2 * 2][0] = r[0];     bh[nf2 * 2][1] = r[1];
            bh[nf2 * 2 + 1][0] = r[2]; bh[nf2 * 2 + 1][1] = r[3];
            ldm_x4_t(r, smem_u32(&Bl[tr_r][wid * 32 + nf2 * 16 + tr_c]));
            bl[nf2 * 2][0] = r[0];     bl[nf2 * 2][1] = r[1];
            bl[nf2 * 2 + 1][0] = r[2]; bl[nf2 * 2 + 1][1] = r[3];
        }
#pragma unroll
        for (int nf = 0; nf < 4; ++nf) {
            mma16816(acc[nf], ah, bh[nf]);
            mma16816(acc[nf], al, bh[nf]);
            mma16816(acc[nf], ah, bl[nf]);
        }
        __syncthreads();
    }

    // epilogue: v = (Wx + acc)*scale -> triple (hi|lo|hi)
#pragma unroll
    for (int nf = 0; nf < 4; ++nf) {
        int n = wid * 32 + nf * 8 + (lane & 3) * 2;
#pragma unroll
        for (int half = 0; half < 2; ++half) {
            int bb = ar + half * 8;
#pragma unroll
            for (int j = 0; j < 2; ++j) {
                long d = d0 + n + j;
                if (d < DD) {
                    float v = (Wx[(long)bb * DD + d] + acc[nf][half * 2 + j]) * scale;
                    __nv_bfloat16 hi, lo;
                    split_bf16(v, hi, lo);
                    int s = (int)(d / EE), e = (int)(d % EE);
                    __nv_bfloat16* o = g03 + ((long)(bb * SS + s)) * KA3;
                    o[e] = hi; o[320 + e] = lo; o[640 + e] = hi;
                }
            }
        }
    }
}

// ---------------- g1^T = W1 · n0^T  (HMMA split-K, atomics) ------------------
// M=512 (h), N=16 (b), K = 720 per block (45 k-tiles), 250 blocks.
__global__ __launch_bounds__(256)
void g1t_hmma_kernel(const __nv_bfloat16* __restrict__ n0hi,
                     const __nv_bfloat16* __restrict__ n0lo,
                     const __nv_bfloat16* __restrict__ W1hi,
                     const __nv_bfloat16* __restrict__ W1lo,
                     float* __restrict__ g1)
{
    __shared__ __nv_bfloat16 Ah[512][16];
    __shared__ __nv_bfloat16 Al[512][16];
    __shared__ __nv_bfloat16 Bh[16][16];
    __shared__ __nv_bfloat16 Bl[16][16];
    const int t = threadIdx.x, lane = t & 31, wid = t >> 5;
    const long k0 = (long)blockIdx.x * 720;
    const int a_r = lane & 15, a_c = (lane >> 4) * 8;
    const int b_r = (lane & 7) + ((lane >> 4) & 1) * 8, b_c = ((lane >> 3) & 1) * 8;
    float acc[4][2][4] = {};

    for (int kt = 0; kt < 45; ++kt) {
        const long kg = k0 + kt * 16;
#pragma unroll
        for (int i = 0; i < 4; ++i) {
            int task = t + i * 256;
            int row = task >> 1, half = (task & 1) * 8;
            long off = (long)row * DD + kg + half;
            *(uint4*)&Ah[row][half] = *(const uint4*)(W1hi + off);
            *(uint4*)&Al[row][half] = *(const uint4*)(W1lo + off);
        }
        if (t < 64) {
            int buf = t >> 5, row = (t & 31) >> 1, half = (t & 1) * 8;
            long off = (long)row * DD + kg + half;
            if (buf == 0) *(uint4*)&Bh[row][half] = *(const uint4*)(n0hi + off);
            else          *(uint4*)&Bl[row][half] = *(const uint4*)(n0lo + off);
        }
        __syncthreads();
        uint32_t bh[4], bl[4];
        ldm_x4(bh, smem_u32(&Bh[b_r][b_c]));
        ldm_x4(bl, smem_u32(&Bl[b_r][b_c]));
#pragma unroll
        for (int mf = 0; mf < 4; ++mf) {
            uint32_t ahf[4], alf[4];
            ldm_x4(ahf, smem_u32(&Ah[wid * 64 + mf * 16 + a_r][a_c]));
            ldm_x4(alf, smem_u32(&Al[wid * 64 + mf * 16 + a_r][a_c]));
#pragma unroll
            for (int nf = 0; nf < 2; ++nf) {
                mma16816(acc[mf][nf], ahf, &bh[nf * 2]);
                mma16816(acc[mf][nf], alf, &bh[nf * 2]);
                mma16816(acc[mf][nf], ahf, &bl[nf * 2]);
            }
        }
        __syncthreads();
    }

    const int cr = lane >> 2, cc = (lane & 3) * 2;
#pragma unroll
    for (int mf = 0; mf < 4; ++mf)
#pragma unroll
        for (int nf = 0; nf < 2; ++nf) {
            int h = wid * 64 + mf * 16 + cr;
            int bb = nf * 8 + cc;
            atomicAdd(&g1[bb * HH + h],           acc[mf][nf][0]);
            atomicAdd(&g1[(bb + 1) * HH + h],     acc[mf][nf][1]);
            atomicAdd(&g1[bb * HH + h + 8],       acc[mf][nf][2]);
            atomicAdd(&g1[(bb + 1) * HH + h + 8], acc[mf][nf][3]);
        }
}

// ---------------- conversions -------------------------------------------------
__global__ void conv_w1_kernel(const float* __restrict__ W1,
                               __nv_bfloat16* __restrict__ hi,
                               __nv_bfloat16* __restrict__ lo)
{
    long i = ((long)blockIdx.x * 256 + threadIdx.x) * 4;
    float4 v = *(const float4*)(W1 + i);
    __nv_bfloat16 h[4], l[4];
    split_bf16(v.x, h[0], l[0]);
    split_bf16(v.y, h[1], l[1]);
    split_bf16(v.z, h[2], l[2]);
    split_bf16(v.w, h[3], l[3]);
    __nv_bfloat162 hh0; hh0.x = h[0]; hh0.y = h[1];
    __nv_bfloat162 hh1; hh1.x = h[2]; hh1.y = h[3];
    __nv_bfloat162 ll0; ll0.x = l[0]; ll0.y = l[1];
    __nv_bfloat162 ll1; ll1.x = l[2]; ll1.y = l[3];
    *(__nv_bfloat162*)(hi + i) = hh0;
    *(__nv_bfloat162*)(hi + i + 2) = hh1;
    *(__nv_bfloat162*)(lo + i) = ll0;
    *(__nv_bfloat162*)(lo + i + 2) = ll1;
}

__global__ void conv_x_kernel(const float* __restrict__ x,
                              __nv_bfloat16* __restrict__ x3,
                              __nv_bfloat16* __restrict__ xT3,
                              __nv_bfloat16* __restrict__ xA3)
{
    int s = blockIdx.x, b = blockIdx.y, e = threadIdx.x;
    __nv_bfloat16 zero = __float2bfloat16(0.f);
    if (s < SS) {
        float v = (e < EE) ? x[((long)b * SS + s) * EE + e] : 0.f;
        __nv_bfloat16 hi, lo;
        split_bf16(v, hi, lo);
        __nv_bfloat16* xr = x3 + ((long)b * SS + s) * KA3;
        xr[e] = hi; xr[320 + e] = hi; xr[640 + e] = lo;
        __nv_bfloat16* xa = xA3 + ((long)b * SS + s) * KA3;
        xa[e] = hi; xa[320 + e] = lo; xa[640 + e] = hi;
        __nv_bfloat16* tr = xT3 + ((long)b * 320 + e) * KP3;
        tr[s] = hi; tr[640 + s] = hi; tr[1280 + s] = lo;
    } else {
        __nv_bfloat16* tr = xT3 + ((long)b * 320 + e) * KP3;
        tr[s] = zero; tr[640 + s] = zero; tr[1280 + s] = zero;
    }
}

__global__ void conv_w0_kernel(const float* __restrict__ W0,
                               __nv_bfloat16* __restrict__ W03)
{
    int f = blockIdx.x, e = threadIdx.x;
    float v = (e < EE) ? W0[f * EE + e] : 0.f;
    __nv_bfloat16 hi, lo;
    split_bf16(v, hi, lo);
    __nv_bfloat16* row = W03 + (long)f * KA3;
    row[e] = hi; row[320 + e] = hi; row[640 + e] = lo;
}

__global__ void conv_wx_kernel(const float* __restrict__ Wx,
                               __nv_bfloat16* __restrict__ g03, float scale)
{
    long r = blockIdx.x;
    int e = threadIdx.x;
    float v = (e < EE) ? scale * Wx[r * EE + e] : 0.f;
    __nv_bfloat16 hi, lo;
    split_bf16(v, hi, lo);
    __nv_bfloat16* out = g03 + r * KA3;
    out[e] = hi; out[320 + e] = lo; out[640 + e] = hi;
}

// ---------------- small kernels ----------------------------------------------
__global__ void init_g1_kernel(const float* __restrict__ b1, const float* __restrict__ n2,
                               const float* __restrict__ W2, float* __restrict__ g1)
{
    int b = blockIdx.x, h = threadIdx.x;
    g1[b * HH + h] = b1[h] + n2[b * NCC] * W2[h] + n2[b * NCC + 1] * W2[HH + h];
}

__global__ void g2_kernel(const float* __restrict__ n1, const float* __restrict__ W2,
                          const float* __restrict__ b2, float* __restrict__ n2n)
{
    int t = threadIdx.x;
    int wid = t >> 5, lane = t & 31;
    int b = wid >> 1, c = wid & 1;
    float s = 0.f;
    for (int h = lane; h < HH; h += 32)
        s += n1[b * HH + h] * W2[c * HH + h];
#pragma unroll
    for (int off = 16; off > 0; off >>= 1)
        s += __shfl_down_sync(0xffffffffu, s, off);
    if (lane == 0) n2n[b * NCC + c] = tanhf(b2[c] + s);
}

__global__ void tanh_n1_kernel(const float* __restrict__ g1, float* __restrict__ n1n,
                               __nv_bfloat16* __restrict__ n1hi,
                               __nv_bfloat16* __restrict__ n1lo)
{
    int i = blockIdx.x * blockDim.x + threadIdx.x;
    float v = tanhf(g1[i]);
    n1n[i] = v;
    __nv_bfloat16 hi, lo;
    split_bf16(v, hi, lo);
    n1hi[i] = hi; n1lo[i] = lo;
}

__global__ void init_step0_kernel(const float* __restrict__ b1, const float* __restrict__ b2,
                                  float* __restrict__ n1n, float* __restrict__ n2n,
                                  __nv_bfloat16* __restrict__ n1hi,
                                  __nv_bfloat16* __restrict__ n1lo)
{
    int b = blockIdx.x, h = threadIdx.x;
    float v = tanhf(b1[h]);
    n1n[b * HH + h] = v;
    __nv_bfloat16 hi, lo;
    split_bf16(v, hi, lo);
    n1hi[b * HH + h] = hi; n1lo[b * HH + h] = lo;
    if (h < NCC) n2n[b * NCC + h] = tanhf(b2[h]);
}

// ---------------- softmax + convert to P3 triple (hi|lo|hi) ------------------
__global__ __launch_bounds__(256)
void softmax_conv_kernel(const float* __restrict__ Praw, __nv_bfloat16* __restrict__ P3)
{
    __shared__ float red[256];
    long r = blockIdx.x;
    const float* p = Praw + r * SS;
    __nv_bfloat16* out = P3 + r * KP3;
    int t = threadIdx.x;

    float a0 = (t < SS)       ? p[t]       : -INFINITY;
    float a1 = (t + 256 < SS) ? p[t + 256] : -INFINITY;
    float a2 = (t + 512 < SS) ? p[t + 512] : -INFINITY;

    float mx = fmaxf(a0, fmaxf(a1, a2));
    red[t] = mx; __syncthreads();
    for (int s = 128; s > 0; s >>= 1) {
        if (t < s) red[t] = fmaxf(red[t], red[t + s]);
        __syncthreads();
    }
    mx = red[0]; __syncthreads();

    float e0 = (t < SS)       ? expf(a0 - mx) : 0.f;
    float e1 = (t + 256 < SS) ? expf(a1 - mx) : 0.f;
    float e2 = (t + 512 < SS) ? expf(a2 - mx) : 0.f;
    red[t] = e0 + e1 + e2; __syncthreads();
    for (int s = 128; s > 0; s >>= 1) {
        if (t < s) red[t] += red[t + s];
        __syncthreads();
    }
    float inv = 1.f / red[0];

    __nv_bfloat16 zero = __float2bfloat16(0.f);
    for (int k = 0; k < 3; ++k) {
        int i = t + k * 256;
        if (i >= 640) break;
        if (i < SS) {
            float v = (k == 0 ? e0 : (k == 1 ? e1 : e2)) * inv;
            __nv_bfloat16 hi, lo;
            split_bf16(v, hi, lo);
            out[i] = hi; out[640 + i] = lo; out[1280 + i] = hi;
        } else {
            out[i] = zero; out[640 + i] = zero; out[1280 + i] = zero;
        }
    }
}

// ---------------- host driver ------------------------------------------------
static float* sym_addr_f(const void* sym)
{
    void* p = nullptr;
    cudaGetSymbolAddress(&p, sym);
    return (float*)p;
}
static __nv_bfloat16* sym_addr_b(const void* sym)
{
    void* p = nullptr;
    cudaGetSymbolAddress(&p, sym);
    return (__nv_bfloat16*)p;
}

extern "C" void kernel_launch(void* const* d_in, const int* in_sizes, int n_in,
                              void* d_out, int out_size)
{
    const float* x   = (const float*)d_in[0];
    const float* W0  = (const float*)d_in[5];
    const float* W1  = (const float*)d_in[6];
    const float* b1  = (const float*)d_in[7];
    const float* W2  = (const float*)d_in[8];
    const float* b2  = (const float*)d_in[9];
    float* out = (float*)d_out;

    float* Wx   = sym_addr_f(g_Wx);
    float* Praw = sym_addr_f(g_Praw);
    float* g1   = sym_addr_f(g_g1);
    float* n0buf[2] = { sym_addr_f(g_n0a), sym_addr_f(g_n0b) };
    float* n1buf[2] = { sym_addr_f(g_n1a), sym_addr_f(g_n1b) };
    float* n2buf[2] = { sym_addr_f(g_n2a), sym_addr_f(g_n2b) };
    __nv_bfloat16* g03  = sym_addr_b(g_g03);
    __nv_bfloat16* x3   = sym_addr_b(g_x3);
    __nv_bfloat16* P3   = sym_addr_b(g_P3);
    __nv_bfloat16* xT3  = sym_addr_b(g_xT3);
    __nv_bfloat16* xA3  = sym_addr_b(g_xA3);
    __nv_bfloat16* W03  = sym_addr_b(g_W03);
    __nv_bfloat16* W1hi = sym_addr_b(g_W1hi);
    __nv_bfloat16* W1lo = sym_addr_b(g_W1lo);
    __nv_bfloat16* n0hi = sym_addr_b(g_n0hi);
    __nv_bfloat16* n0lo = sym_addr_b(g_n0lo);
    __nv_bfloat16* n1hi = sym_addr_b(g_n1hi);
    __nv_bfloat16* n1lo = sym_addr_b(g_n1lo);

    const float scale = 1.0f / sqrtf((float)EE);

    // one-time conversions
    {
        dim3 g(640, BB);
        conv_x_kernel<<<g, 320>>>(x, x3, xT3, xA3);
    }
    conv_w0_kernel<<<EE, 320>>>(W0, W03);
    conv_w1_kernel<<<90000, 256>>>(W1, W1hi, W1lo);

    // Wx = x @ W0^T  via HMMA (M=9600, N=300, K3=960)
    {
        dim3 grid(3, 75, 1);
        hmma_gemm_kernel<<<grid, 256>>>(
            xA3, W03, Wx, nullptr, nullptr,
            KA3, 0, BB * SS,
            KA3, 0, EE,
            EE, 0, BB * SS, EE,
            15);
    }

    const float* n0c = nullptr;
    const float* n1c = nullptr;
    const float* n2c = nullptr;

    for (int step = 0; step < TT; ++step) {
        float* n0n = n0buf[step & 1];
        float* n1n = n1buf[step & 1];
        float* n2n = n2buf[step & 1];

        if (step == 0) {
            init_step0_kernel<<<BB, HH>>>(b1, b2, n1n, n2n, n1hi, n1lo);
            conv_wx_kernel<<<BB * SS, 320>>>(Wx, g03, scale);
        } else {
            init_g1_kernel<<<BB, HH>>>(b1, n2c, W2, g1);
            g2_kernel<<<1, 1024>>>(n1c, W2, b2, n2n);
            g0_hmma_kernel<<<704, 256>>>(n1hi, n1lo, W1hi, W1lo, Wx, g03, scale);
            g1t_hmma_kernel<<<250, 256>>>(n0hi, n0lo, W1hi, W1lo, g1);
            tanh_n1_kernel<<<BB, HH>>>(g1, n1n, n1hi, n1lo);
        }

        // scores = (scale*g0) @ x^T   [HMMA, triple-K bf16]
        {
            dim3 grid(5, 5, BB);
            hmma_gemm_kernel<<<grid, 256>>>(
                g03, x3, Praw, nullptr, nullptr,
                KA3, (long)SS * KA3, SS,
                KA3, (long)SS * KA3, SS,
                SS, (long)SS * SS, SS, SS,
                15);
        }
        softmax_conv_kernel<<<BB * SS, 256>>>(Praw, P3);
        // n0n = P @ x   [HMMA] (+ bf16 hi/lo for next step's g1)
        {
            dim3 grid(3, 5, BB);
            hmma_gemm_kernel<<<grid, 256>>>(
                P3, xT3, n0n, n0hi, n0lo,
                KP3, (long)SS * KP3, SS,
                KP3, (long)320 * KP3, 320,
                EE, (long)SS * EE, SS, EE,
                30);
        }

        n0c = n0n; n1c = n1n; n2c = n2n;
    }

    // pack output: n0 | n1 | n2
    cudaMemcpyAsync(out, n0c, (size_t)BB * SS * EE * sizeof(float),
                    cudaMemcpyDeviceToDevice, 0);
    cudaMemcpyAsync(out + (long)BB * SS * EE, n1c, (size_t)BB * HH * sizeof(float),
                    cudaMemcpyDeviceToDevice, 0);
    cudaMemcpyAsync(out + (long)BB * SS * EE + BB * HH, n2c,
                    (size_t)BB * NCC * sizeof(float), cudaMemcpyDeviceToDevice, 0);
}

// round 6
// speedup vs baseline: 1.9129x; 1.1298x over previous
#include <cuda_runtime.h>
#include <cuda_bf16.h>
#include <math.h>
#include <stdint.h>

// Problem constants
#define BB   16
#define SS   600
#define EE   300
#define HH   512
#define NCC  2
#define DD   180000L
#define TT   3

#define KA3   960    // K=300-class triple (3 x 320)
#define KP3   1920   // K=600-class triple (3 x 640)

// fused W1 kernel tiling
#define DSLICE 256
#define HCHUNK 32
#define NCHUNK (HH / HCHUNK)           // 16
#define NDBLK  ((int)((DD + DSLICE - 1) / DSLICE))   // 704

// ---------------- scratch (device globals) -----------------------------------
__device__ float g_Wx [BB * SS * EE];
__device__ float g_Praw[BB * SS * SS];
__device__ float g_n0a[BB * SS * EE];
__device__ float g_n0b[BB * SS * EE];
__device__ float g_n1a[BB * HH];
__device__ float g_n1b[BB * HH];
__device__ float g_n2a[BB * NCC];
__device__ float g_n2b[BB * NCC];
__device__ float g_g1 [BB * HH];
__device__ __nv_bfloat16 g_g03[(size_t)BB * SS * KA3];
__device__ __nv_bfloat16 g_x3 [(size_t)BB * SS * KA3];
__device__ __nv_bfloat16 g_P3 [(size_t)BB * SS * KP3];
__device__ __nv_bfloat16 g_xT3[(size_t)BB * 320 * KP3];
__device__ __nv_bfloat16 g_xA3[(size_t)BB * SS * KA3];
__device__ __nv_bfloat16 g_W03[(size_t)EE * KA3];
__device__ __nv_bfloat16 g_n0hi[(size_t)BB * DD + 512];   // pad: OOB-safe B loads
__device__ __nv_bfloat16 g_n0lo[(size_t)BB * DD + 512];
__device__ __nv_bfloat16 g_n1hi[BB * HH];
__device__ __nv_bfloat16 g_n1lo[BB * HH];

// ---------------- helpers -----------------------------------------------------
__device__ __forceinline__ uint32_t smem_u32(const void* p) {
    uint32_t a;
    asm("{ .reg .u64 t; cvta.to.shared.u64 t, %1; cvt.u32.u64 %0, t; }" : "=r"(a) : "l"(p));
    return a;
}
__device__ __forceinline__ void ldm_x4(uint32_t* r, uint32_t addr) {
    asm volatile("ldmatrix.sync.aligned.m8n8.x4.shared.b16 {%0,%1,%2,%3}, [%4];"
                 : "=r"(r[0]), "=r"(r[1]), "=r"(r[2]), "=r"(r[3]) : "r"(addr));
}
__device__ __forceinline__ void ldm_x4_t(uint32_t* r, uint32_t addr) {
    asm volatile("ldmatrix.sync.aligned.m8n8.x4.trans.shared.b16 {%0,%1,%2,%3}, [%4];"
                 : "=r"(r[0]), "=r"(r[1]), "=r"(r[2]), "=r"(r[3]) : "r"(addr));
}
__device__ __forceinline__ void mma16816(float* c, const uint32_t* a, const uint32_t* b) {
    asm volatile(
        "mma.sync.aligned.m16n8k16.row.col.f32.bf16.bf16.f32 "
        "{%0,%1,%2,%3}, {%4,%5,%6,%7}, {%8,%9}, {%0,%1,%2,%3};"
        : "+f"(c[0]), "+f"(c[1]), "+f"(c[2]), "+f"(c[3])
        : "r"(a[0]), "r"(a[1]), "r"(a[2]), "r"(a[3]), "r"(b[0]), "r"(b[1]));
}
__device__ __forceinline__ void split_bf16(float v, __nv_bfloat16& hi, __nv_bfloat16& lo) {
    hi = __float2bfloat16(v);
    lo = __float2bfloat16(v - __bfloat162float(hi));
}

// ============ fused per-step W1 kernel =======================================
// Streams W1 (fp32) ONCE; computes
//   g03 <- (Wx + n1 @ W1) * scale   (triple bf16 layout)
//   g1  += n0flat @ W1^T            (fp32 atomics)
// Block: 256 threads; d-slice 256 cols; h-chunks of 32.
// Warps 0-3: g0 (64 d-cols each). Warps 4-7: g1 (64-d K-slice each).
__global__ __launch_bounds__(256)
void fused_w1_kernel(const float* __restrict__ W1,
                     const __nv_bfloat16* __restrict__ n1hi,
                     const __nv_bfloat16* __restrict__ n1lo,
                     const __nv_bfloat16* __restrict__ n0hi,
                     const __nv_bfloat16* __restrict__ n0lo,
                     const float* __restrict__ Wx,
                     float* __restrict__ g1,
                     __nv_bfloat16* __restrict__ g03,
                     float scale)
{
    __shared__ __align__(16) __nv_bfloat16 tH[HCHUNK][DSLICE + 8];
    __shared__ __align__(16) __nv_bfloat16 tL[HCHUNK][DSLICE + 8];
    __shared__ float g1buf[HCHUNK][17];

    const int t = threadIdx.x, lane = t & 31, wid = t >> 5;
    const long d0 = (long)blockIdx.x * DSLICE;

    uint4 pre[8];

    // ---- load chunk hc of W1 (fp32) into registers
    auto issue_loads = [&](int hc) {
#pragma unroll
        for (int i = 0; i < 8; ++i) {
            int f = t + i * 256;            // 0..2047 float4 slots
            int row = f >> 6, c4 = f & 63;
            long d = d0 + (long)c4 * 4;
            if (d + 4 <= DD)
                pre[i] = *(const uint4*)(W1 + (long)(hc * HCHUNK + row) * DD + d);
            else
                pre[i] = make_uint4(0, 0, 0, 0);
        }
    };
    // ---- split fp32 regs -> hi/lo bf16 smem tiles
    auto store_tiles = [&]() {
#pragma unroll
        for (int i = 0; i < 8; ++i) {
            int f = t + i * 256;
            int row = f >> 6, c4 = f & 63;
            float4 v = *(float4*)&pre[i];
            __nv_bfloat16 hh[4], ll[4];
            split_bf16(v.x, hh[0], ll[0]);
            split_bf16(v.y, hh[1], ll[1]);
            split_bf16(v.z, hh[2], ll[2]);
            split_bf16(v.w, hh[3], ll[3]);
            *(uint2*)&tH[row][c4 * 4] = *(uint2*)hh;
            *(uint2*)&tL[row][c4 * 4] = *(uint2*)ll;
        }
    };

    float accg0[8][4] = {};

    issue_loads(0);
    store_tiles();
    for (int i = t; i < HCHUNK * 17; i += 256) ((float*)g1buf)[i] = 0.f;
    __syncthreads();

    for (int hc = 0; hc < NCHUNK; ++hc) {
        if (hc + 1 < NCHUNK) issue_loads(hc + 1);

        if (wid < 4) {
            // ---- g0: M=16 (batch), N=64 d-cols, K=32 (h chunk), 3-term
            const int tr_r = lane & 15, tr_c = (lane >> 4) * 8;
            const int ar = lane >> 2, ac = (lane & 3) * 2;
#pragma unroll
            for (int ks = 0; ks < 2; ++ks) {
                int kb = hc * HCHUNK + ks * 16;
                uint32_t ah[4], al[4];
                ah[0] = *(const uint32_t*)(n1hi + ar * HH + kb + ac);
                ah[1] = *(const uint32_t*)(n1hi + (ar + 8) * HH + kb + ac);
                ah[2] = *(const uint32_t*)(n1hi + ar * HH + kb + ac + 8);
                ah[3] = *(const uint32_t*)(n1hi + (ar + 8) * HH + kb + ac + 8);
                al[0] = *(const uint32_t*)(n1lo + ar * HH + kb + ac);
                al[1] = *(const uint32_t*)(n1lo + (ar + 8) * HH + kb + ac);
                al[2] = *(const uint32_t*)(n1lo + ar * HH + kb + ac + 8);
                al[3] = *(const uint32_t*)(n1lo + (ar + 8) * HH + kb + ac + 8);
#pragma unroll
                for (int q = 0; q < 4; ++q) {
                    uint32_t bh[4], bl[4];
                    ldm_x4_t(bh, smem_u32(&tH[ks * 16 + tr_r][wid * 64 + q * 16 + tr_c]));
                    ldm_x4_t(bl, smem_u32(&tL[ks * 16 + tr_r][wid * 64 + q * 16 + tr_c]));
                    mma16816(accg0[q * 2],     ah, &bh[0]);
                    mma16816(accg0[q * 2],     al, &bh[0]);
                    mma16816(accg0[q * 2],     ah, &bl[0]);
                    mma16816(accg0[q * 2 + 1], ah, &bh[2]);
                    mma16816(accg0[q * 2 + 1], al, &bh[2]);
                    mma16816(accg0[q * 2 + 1], ah, &bl[2]);
                }
            }
        } else {
            // ---- g1: M=32 (h chunk), N=16 (batch), K=64 d-slice per warp
            const int w = wid - 4;
            const int a_r = lane & 15, a_c = (lane >> 4) * 8;
            float acc1[2][2][4] = {};
#pragma unroll
            for (int ks = 0; ks < 4; ++ks) {
                long dk = d0 + w * 64 + ks * 16;
                uint32_t bh[2][2], bl[2][2];
#pragma unroll
                for (int nt = 0; nt < 2; ++nt) {
                    long baddr = (long)(nt * 8 + (lane >> 2)) * DD + dk + (lane & 3) * 2;
                    bh[nt][0] = *(const uint32_t*)(n0hi + baddr);
                    bh[nt][1] = *(const uint32_t*)(n0hi + baddr + 8);
                    bl[nt][0] = *(const uint32_t*)(n0lo + baddr);
                    bl[nt][1] = *(const uint32_t*)(n0lo + baddr + 8);
                }
#pragma unroll
                for (int mt = 0; mt < 2; ++mt) {
                    uint32_t ahf[4], alf[4];
                    ldm_x4(ahf, smem_u32(&tH[mt * 16 + a_r][w * 64 + ks * 16 + a_c]));
                    ldm_x4(alf, smem_u32(&tL[mt * 16 + a_r][w * 64 + ks * 16 + a_c]));
#pragma unroll
                    for (int nt = 0; nt < 2; ++nt) {
                        mma16816(acc1[mt][nt], ahf, bh[nt]);
                        mma16816(acc1[mt][nt], alf, bh[nt]);
                        mma16816(acc1[mt][nt], ahf, bl[nt]);
                    }
                }
            }
            const int cr = lane >> 2, cc = (lane & 3) * 2;
#pragma unroll
            for (int mt = 0; mt < 2; ++mt)
#pragma unroll
                for (int nt = 0; nt < 2; ++nt) {
                    atomicAdd(&g1buf[mt * 16 + cr][nt * 8 + cc],         acc1[mt][nt][0]);
                    atomicAdd(&g1buf[mt * 16 + cr][nt * 8 + cc + 1],     acc1[mt][nt][1]);
                    atomicAdd(&g1buf[mt * 16 + cr + 8][nt * 8 + cc],     acc1[mt][nt][2]);
                    atomicAdd(&g1buf[mt * 16 + cr + 8][nt * 8 + cc + 1], acc1[mt][nt][3]);
                }
        }
        __syncthreads();

        // flush g1buf to global (each thread owns 2 entries; read then zero)
#pragma unroll
        for (int i = 0; i < 2; ++i) {
            int idx = t + i * 256;
            int h = idx >> 4, b = idx & 15;
            float v = g1buf[h][b];
            if (v != 0.f) atomicAdd(&g1[b * HH + hc * HCHUNK + h], v);
            g1buf[h][b] = 0.f;
        }
        if (hc + 1 < NCHUNK) store_tiles();
        __syncthreads();
    }

    // ---- g0 epilogue: (Wx + acc) * scale -> g03 triple (hi|lo|hi)
    if (wid < 4) {
        const int ar = lane >> 2, cc = (lane & 3) * 2;
#pragma unroll
        for (int q = 0; q < 8; ++q) {
            int dn = wid * 64 + q * 8 + cc;
            long d = d0 + dn;
            if (d + 1 < DD) {
                int s = (int)(d / EE), e = (int)(d % EE);   // e even -> pair same row
#pragma unroll
                for (int half = 0; half < 2; ++half) {
                    int bb = ar + half * 8;
                    float2 wx = *(const float2*)(Wx + (long)bb * DD + d);
                    float v0 = (wx.x + accg0[q][half * 2])     * scale;
                    float v1 = (wx.y + accg0[q][half * 2 + 1]) * scale;
                    __nv_bfloat16 hi[2], lo[2];
                    split_bf16(v0, hi[0], lo[0]);
                    split_bf16(v1, hi[1], lo[1]);
                    __nv_bfloat16* o = g03 + ((long)(bb * SS + s)) * KA3;
                    *(uint32_t*)&o[e]       = *(uint32_t*)hi;
                    *(uint32_t*)&o[320 + e] = *(uint32_t*)lo;
                    *(uint32_t*)&o[640 + e] = *(uint32_t*)hi;
                }
            }
        }
    }
}

// ---------------- generic HMMA GEMM: C = A3 · B3^T (triple-K bf16, NT) -------
__global__ __launch_bounds__(256)
void hmma_gemm_kernel(const __nv_bfloat16* __restrict__ A3,
                      const __nv_bfloat16* __restrict__ B3,
                      float* __restrict__ C,
                      __nv_bfloat16* __restrict__ Chi,
                      __nv_bfloat16* __restrict__ Clo,
                      int ldA, long bsA, int rowsA,
                      int ldB, long bsB, int rowsB,
                      int ldC, long bsC, int Mvalid, int Nvalid,
                      int kchunks)
{
    __shared__ __nv_bfloat16 As[128][72];
    __shared__ __nv_bfloat16 Bs[128][72];
    const int t = threadIdx.x, lane = t & 31, wid = t >> 5;
    const int wm = wid >> 2, wn = wid & 3;
    const int b = blockIdx.z, m0 = blockIdx.y * 128, n0 = blockIdx.x * 128;
    const __nv_bfloat16* Ab = A3 + (long)b * bsA;
    const __nv_bfloat16* Bb = B3 + (long)b * bsB;
    float acc[4][4][4] = {};
    const uint4 zz = make_uint4(0, 0, 0, 0);

    const int a_lm = lane & 15;
    const int a_lk = (lane >> 4) * 8;
    const int b_ln = (lane & 7) + ((lane >> 4) & 1) * 8;
    const int b_lk = ((lane >> 3) & 1) * 8;

    for (int ch = 0; ch < kchunks; ++ch) {
        const long kg = (long)ch * 64;
#pragma unroll
        for (int i = 0; i < 4; ++i) {
            int idx = t + i * 256;
            int row = idx >> 3, q = idx & 7;
            const uint4* pa = (const uint4*)(Ab + (long)(m0 + row) * ldA + kg + q * 8);
            const uint4* pb = (const uint4*)(Bb + (long)(n0 + row) * ldB + kg + q * 8);
            *(uint4*)&As[row][q * 8] = (m0 + row < rowsA) ? *pa : zz;
            *(uint4*)&Bs[row][q * 8] = (n0 + row < rowsB) ? *pb : zz;
        }
        __syncthreads();
#pragma unroll
        for (int ks = 0; ks < 4; ++ks) {
            uint32_t af[4][4], bf[4][2];
#pragma unroll
            for (int mf = 0; mf < 4; ++mf)
                ldm_x4(af[mf], smem_u32(&As[wm * 64 + mf * 16 + a_lm][ks * 16 + a_lk]));
#pragma unroll
            for (int nf2 = 0; nf2 < 2; ++nf2) {
                uint32_t r[4];
                ldm_x4(r, smem_u32(&Bs[wn * 32 + nf2 * 16 + b_ln][ks * 16 + b_lk]));
                bf[nf2 * 2][0] = r[0];     bf[nf2 * 2][1] = r[1];
                bf[nf2 * 2 + 1][0] = r[2]; bf[nf2 * 2 + 1][1] = r[3];
            }
#pragma unroll
            for (int mf = 0; mf < 4; ++mf)
#pragma unroll
                for (int nf = 0; nf < 4; ++nf)
                    mma16816(acc[mf][nf], af[mf], bf[nf]);
        }
        __syncthreads();
    }

    float* Cb = C + (long)b * bsC;
    const int mbase = m0 + wm * 64, nbase = n0 + wn * 32;
#pragma unroll
    for (int mf = 0; mf < 4; ++mf) {
#pragma unroll
        for (int nf = 0; nf < 4; ++nf) {
            int m = mbase + mf * 16 + (lane >> 2);
            int n = nbase + nf * 8 + (lane & 3) * 2;
            if (n < Nvalid) {
#pragma unroll
                for (int half = 0; half < 2; ++half) {
                    int mm = m + half * 8;
                    float v0 = acc[mf][nf][half * 2], v1 = acc[mf][nf][half * 2 + 1];
                    if (mm < Mvalid) {
                        long o = (long)mm * ldC + n;
                        *(float2*)&Cb[o] = make_float2(v0, v1);
                        if (Chi) {
                            __nv_bfloat16 h0, l0, h1, l1;
                            split_bf16(v0, h0, l0);
                            split_bf16(v1, h1, l1);
                            __nv_bfloat162 hh; hh.x = h0; hh.y = h1;
                            __nv_bfloat162 ll; ll.x = l0; ll.y = l1;
                            *(__nv_bfloat162*)&Chi[(long)b * bsC + o] = hh;
                            *(__nv_bfloat162*)&Clo[(long)b * bsC + o] = ll;
                        }
                    }
                }
            }
        }
    }
}

// ---------------- conversions -------------------------------------------------
__global__ void conv_x_kernel(const float* __restrict__ x,
                              __nv_bfloat16* __restrict__ x3,
                              __nv_bfloat16* __restrict__ xT3,
                              __nv_bfloat16* __restrict__ xA3)
{
    int s = blockIdx.x, b = blockIdx.y, e = threadIdx.x;
    __nv_bfloat16 zero = __float2bfloat16(0.f);
    if (s < SS) {
        float v = (e < EE) ? x[((long)b * SS + s) * EE + e] : 0.f;
        __nv_bfloat16 hi, lo;
        split_bf16(v, hi, lo);
        __nv_bfloat16* xr = x3 + ((long)b * SS + s) * KA3;
        xr[e] = hi; xr[320 + e] = hi; xr[640 + e] = lo;
        __nv_bfloat16* xa = xA3 + ((long)b * SS + s) * KA3;
        xa[e] = hi; xa[320 + e] = lo; xa[640 + e] = hi;
        __nv_bfloat16* tr = xT3 + ((long)b * 320 + e) * KP3;
        tr[s] = hi; tr[640 + s] = hi; tr[1280 + s] = lo;
    } else {
        __nv_bfloat16* tr = xT3 + ((long)b * 320 + e) * KP3;
        tr[s] = zero; tr[640 + s] = zero; tr[1280 + s] = zero;
    }
}

__global__ void conv_w0_kernel(const float* __restrict__ W0,
                               __nv_bfloat16* __restrict__ W03)
{
    int f = blockIdx.x, e = threadIdx.x;
    float v = (e < EE) ? W0[f * EE + e] : 0.f;
    __nv_bfloat16 hi, lo;
    split_bf16(v, hi, lo);
    __nv_bfloat16* row = W03 + (long)f * KA3;
    row[e] = hi; row[320 + e] = hi; row[640 + e] = lo;
}

__global__ void conv_wx_kernel(const float* __restrict__ Wx,
                               __nv_bfloat16* __restrict__ g03, float scale)
{
    long r = blockIdx.x;
    int e = threadIdx.x;
    float v = (e < EE) ? scale * Wx[r * EE + e] : 0.f;
    __nv_bfloat16 hi, lo;
    split_bf16(v, hi, lo);
    __nv_bfloat16* out = g03 + r * KA3;
    out[e] = hi; out[320 + e] = lo; out[640 + e] = hi;
}

// ---------------- small kernels ----------------------------------------------
__global__ void init_g1_kernel(const float* __restrict__ b1, const float* __restrict__ n2,
                               const float* __restrict__ W2, float* __restrict__ g1)
{
    int b = blockIdx.x, h = threadIdx.x;
    g1[b * HH + h] = b1[h] + n2[b * NCC] * W2[h] + n2[b * NCC + 1] * W2[HH + h];
}

__global__ void g2_kernel(const float* __restrict__ n1, const float* __restrict__ W2,
                          const float* __restrict__ b2, float* __restrict__ n2n)
{
    int t = threadIdx.x;
    int wid = t >> 5, lane = t & 31;
    int b = wid >> 1, c = wid & 1;
    float s = 0.f;
    for (int h = lane; h < HH; h += 32)
        s += n1[b * HH + h] * W2[c * HH + h];
#pragma unroll
    for (int off = 16; off > 0; off >>= 1)
        s += __shfl_down_sync(0xffffffffu, s, off);
    if (lane == 0) n2n[b * NCC + c] = tanhf(b2[c] + s);
}

__global__ void tanh_n1_kernel(const float* __restrict__ g1, float* __restrict__ n1n,
                               __nv_bfloat16* __restrict__ n1hi,
                               __nv_bfloat16* __restrict__ n1lo)
{
    int i = blockIdx.x * blockDim.x + threadIdx.x;
    float v = tanhf(g1[i]);
    n1n[i] = v;
    __nv_bfloat16 hi, lo;
    split_bf16(v, hi, lo);
    n1hi[i] = hi; n1lo[i] = lo;
}

__global__ void init_step0_kernel(const float* __restrict__ b1, const float* __restrict__ b2,
                                  float* __restrict__ n1n, float* __restrict__ n2n,
                                  __nv_bfloat16* __restrict__ n1hi,
                                  __nv_bfloat16* __restrict__ n1lo)
{
    int b = blockIdx.x, h = threadIdx.x;
    float v = tanhf(b1[h]);
    n1n[b * HH + h] = v;
    __nv_bfloat16 hi, lo;
    split_bf16(v, hi, lo);
    n1hi[b * HH + h] = hi; n1lo[b * HH + h] = lo;
    if (h < NCC) n2n[b * NCC + h] = tanhf(b2[h]);
}

// ---------------- softmax + convert to P3 triple (hi|lo|hi) ------------------
__global__ __launch_bounds__(256)
void softmax_conv_kernel(const float* __restrict__ Praw, __nv_bfloat16* __restrict__ P3)
{
    __shared__ float red[256];
    long r = blockIdx.x;
    const float* p = Praw + r * SS;
    __nv_bfloat16* out = P3 + r * KP3;
    int t = threadIdx.x;

    float a0 = (t < SS)       ? p[t]       : -INFINITY;
    float a1 = (t + 256 < SS) ? p[t + 256] : -INFINITY;
    float a2 = (t + 512 < SS) ? p[t + 512] : -INFINITY;

    float mx = fmaxf(a0, fmaxf(a1, a2));
    red[t] = mx; __syncthreads();
    for (int s = 128; s > 0; s >>= 1) {
        if (t < s) red[t] = fmaxf(red[t], red[t + s]);
        __syncthreads();
    }
    mx = red[0]; __syncthreads();

    float e0 = (t < SS)       ? expf(a0 - mx) : 0.f;
    float e1 = (t + 256 < SS) ? expf(a1 - mx) : 0.f;
    float e2 = (t + 512 < SS) ? expf(a2 - mx) : 0.f;
    red[t] = e0 + e1 + e2; __syncthreads();
    for (int s = 128; s > 0; s >>= 1) {
        if (t < s) red[t] += red[t + s];
        __syncthreads();
    }
    float inv = 1.f / red[0];

    __nv_bfloat16 zero = __float2bfloat16(0.f);
    for (int k = 0; k < 3; ++k) {
        int i = t + k * 256;
        if (i >= 640) break;
        if (i < SS) {
            float v = (k == 0 ? e0 : (k == 1 ? e1 : e2)) * inv;
            __nv_bfloat16 hi, lo;
            split_bf16(v, hi, lo);
            out[i] = hi; out[640 + i] = lo; out[1280 + i] = hi;
        } else {
            out[i] = zero; out[640 + i] = zero; out[1280 + i] = zero;
        }
    }
}

// ---------------- host driver ------------------------------------------------
static float* sym_addr_f(const void* sym)
{
    void* p = nullptr;
    cudaGetSymbolAddress(&p, sym);
    return (float*)p;
}
static __nv_bfloat16* sym_addr_b(const void* sym)
{
    void* p = nullptr;
    cudaGetSymbolAddress(&p, sym);
    return (__nv_bfloat16*)p;
}

extern "C" void kernel_launch(void* const* d_in, const int* in_sizes, int n_in,
                              void* d_out, int out_size)
{
    const float* x   = (const float*)d_in[0];
    const float* W0  = (const float*)d_in[5];
    const float* W1  = (const float*)d_in[6];
    const float* b1  = (const float*)d_in[7];
    const float* W2  = (const float*)d_in[8];
    const float* b2  = (const float*)d_in[9];
    float* out = (float*)d_out;

    float* Wx   = sym_addr_f(g_Wx);
    float* Praw = sym_addr_f(g_Praw);
    float* g1   = sym_addr_f(g_g1);
    float* n0buf[2] = { sym_addr_f(g_n0a), sym_addr_f(g_n0b) };
    float* n1buf[2] = { sym_addr_f(g_n1a), sym_addr_f(g_n1b) };
    float* n2buf[2] = { sym_addr_f(g_n2a), sym_addr_f(g_n2b) };
    __nv_bfloat16* g03  = sym_addr_b(g_g03);
    __nv_bfloat16* x3   = sym_addr_b(g_x3);
    __nv_bfloat16* P3   = sym_addr_b(g_P3);
    __nv_bfloat16* xT3  = sym_addr_b(g_xT3);
    __nv_bfloat16* xA3  = sym_addr_b(g_xA3);
    __nv_bfloat16* W03  = sym_addr_b(g_W03);
    __nv_bfloat16* n0hi = sym_addr_b(g_n0hi);
    __nv_bfloat16* n0lo = sym_addr_b(g_n0lo);
    __nv_bfloat16* n1hi = sym_addr_b(g_n1hi);
    __nv_bfloat16* n1lo = sym_addr_b(g_n1lo);

    const float scale = 1.0f / sqrtf((float)EE);

    // one-time conversions
    {
        dim3 g(640, BB);
        conv_x_kernel<<<g, 320>>>(x, x3, xT3, xA3);
    }
    conv_w0_kernel<<<EE, 320>>>(W0, W03);

    // Wx = x @ W0^T via HMMA (M=9600, N=300, K3=960)
    {
        dim3 grid(3, 75, 1);
        hmma_gemm_kernel<<<grid, 256>>>(
            xA3, W03, Wx, nullptr, nullptr,
            KA3, 0, BB * SS,
            KA3, 0, EE,
            EE, 0, BB * SS, EE,
            15);
    }

    const float* n0c = nullptr;
    const float* n1c = nullptr;
    const float* n2c = nullptr;

    for (int step = 0; step < TT; ++step) {
        float* n0n = n0buf[step & 1];
        float* n1n = n1buf[step & 1];
        float* n2n = n2buf[step & 1];

        if (step == 0) {
            init_step0_kernel<<<BB, HH>>>(b1, b2, n1n, n2n, n1hi, n1lo);
            conv_wx_kernel<<<BB * SS, 320>>>(Wx, g03, scale);
        } else {
            init_g1_kernel<<<BB, HH>>>(b1, n2c, W2, g1);
            g2_kernel<<<1, 1024>>>(n1c, W2, b2, n2n);
            fused_w1_kernel<<<NDBLK, 256>>>(W1, n1hi, n1lo, n0hi, n0lo,
                                            Wx, g1, g03, scale);
            tanh_n1_kernel<<<BB, HH>>>(g1, n1n, n1hi, n1lo);
        }

        // scores = (scale*g0) @ x^T  [HMMA triple-K]
        {
            dim3 grid(5, 5, BB);
            hmma_gemm_kernel<<<grid, 256>>>(
                g03, x3, Praw, nullptr, nullptr,
                KA3, (long)SS * KA3, SS,
                KA3, (long)SS * KA3, SS,
                SS, (long)SS * SS, SS, SS,
                15);
        }
        softmax_conv_kernel<<<BB * SS, 256>>>(Praw, P3);
        // n0n = P @ x  [HMMA] (+ bf16 hi/lo for next step's g1)
        {
            dim3 grid(3, 5, BB);
            hmma_gemm_kernel<<<grid, 256>>>(
                P3, xT3, n0n, n0hi, n0lo,
                KP3, (long)SS * KP3, SS,
                KP3, (long)320 * KP3, 320,
                EE, (long)SS * EE, SS, EE,
                30);
        }

        n0c = n0n; n1c = n1n; n2c = n2n;
    }

    // pack output: n0 | n1 | n2
    cudaMemcpyAsync(out, n0c, (size_t)BB * SS * EE * sizeof(float),
                    cudaMemcpyDeviceToDevice, 0);
    cudaMemcpyAsync(out + (long)BB * SS * EE, n1c, (size_t)BB * HH * sizeof(float),
                    cudaMemcpyDeviceToDevice, 0);
    cudaMemcpyAsync(out + (long)BB * SS * EE + BB * HH, n2c,
                    (size_t)BB * NCC * sizeof(float), cudaMemcpyDeviceToDevice, 0);
}

// round 7
// speedup vs baseline: 2.1490x; 1.1234x over previous
#include <cuda_runtime.h>
#include <cuda_bf16.h>
#include <math.h>
#include <stdint.h>

// Problem constants
#define BB   16
#define SS   600
#define EE   300
#define HH   512
#define NCC  2
#define DD   180000L
#define TT   3

#define KA3   960    // K=300-class triple (3 x 320)
#define KP3   1920   // K=600-class triple (3 x 640)

// fused W1 kernel tiling
#define DSLICE 256
#define HCHUNK 32
#define NCHUNK (HH / HCHUNK)
#define NDBLK  ((int)((DD + DSLICE - 1) / DSLICE))

// ---------------- scratch (device globals) -----------------------------------
__device__ float g_Wx [BB * SS * EE];
__device__ float g_Praw[BB * SS * SS];
__device__ float g_n0a[BB * SS * EE];
__device__ float g_n0b[BB * SS * EE];
__device__ float g_n1a[BB * HH];
__device__ float g_n1b[BB * HH];
__device__ float g_n2a[BB * NCC];
__device__ float g_n2b[BB * NCC];
__device__ float g_g1 [BB * HH];
__device__ __nv_bfloat16 g_g03[(size_t)BB * SS * KA3];
__device__ __nv_bfloat16 g_x3 [(size_t)BB * SS * KA3];
__device__ __nv_bfloat16 g_P3 [(size_t)BB * SS * KP3];
__device__ __nv_bfloat16 g_xT3[(size_t)BB * 320 * KP3];
__device__ __nv_bfloat16 g_xA3[(size_t)BB * SS * KA3];
__device__ __nv_bfloat16 g_W03[(size_t)EE * KA3];
__device__ __nv_bfloat16 g_n0hi[(size_t)BB * DD + 512];
__device__ __nv_bfloat16 g_n0lo[(size_t)BB * DD + 512];
__device__ __nv_bfloat16 g_n1hi[BB * HH];
__device__ __nv_bfloat16 g_n1lo[BB * HH];

// ---------------- helpers -----------------------------------------------------
__device__ __forceinline__ uint32_t smem_u32(const void* p) {
    uint32_t a;
    asm("{ .reg .u64 t; cvta.to.shared.u64 t, %1; cvt.u32.u64 %0, t; }" : "=r"(a) : "l"(p));
    return a;
}
__device__ __forceinline__ void ldm_x4(uint32_t* r, uint32_t addr) {
    asm volatile("ldmatrix.sync.aligned.m8n8.x4.shared.b16 {%0,%1,%2,%3}, [%4];"
                 : "=r"(r[0]), "=r"(r[1]), "=r"(r[2]), "=r"(r[3]) : "r"(addr));
}
__device__ __forceinline__ void ldm_x4_t(uint32_t* r, uint32_t addr) {
    asm volatile("ldmatrix.sync.aligned.m8n8.x4.trans.shared.b16 {%0,%1,%2,%3}, [%4];"
                 : "=r"(r[0]), "=r"(r[1]), "=r"(r[2]), "=r"(r[3]) : "r"(addr));
}
__device__ __forceinline__ void mma16816(float* c, const uint32_t* a, const uint32_t* b) {
    asm volatile(
        "mma.sync.aligned.m16n8k16.row.col.f32.bf16.bf16.f32 "
        "{%0,%1,%2,%3}, {%4,%5,%6,%7}, {%8,%9}, {%0,%1,%2,%3};"
        : "+f"(c[0]), "+f"(c[1]), "+f"(c[2]), "+f"(c[3])
        : "r"(a[0]), "r"(a[1]), "r"(a[2]), "r"(a[3]), "r"(b[0]), "r"(b[1]));
}
__device__ __forceinline__ void split_bf16(float v, __nv_bfloat16& hi, __nv_bfloat16& lo) {
    hi = __float2bfloat16(v);
    lo = __float2bfloat16(v - __bfloat162float(hi));
}
__device__ __forceinline__ void cp_async16(uint32_t dst, const void* src, int bytes) {
    asm volatile("cp.async.cg.shared.global [%0], [%1], 16, %2;"
                 :: "r"(dst), "l"(src), "r"(bytes));
}
__device__ __forceinline__ void cp_commit() {
    asm volatile("cp.async.commit_group;");
}
template <int N>
__device__ __forceinline__ void cp_wait() {
    asm volatile("cp.async.wait_group %0;" :: "n"(N));
}

// ============ fused per-step W1 kernel (unchanged from R6) ===================
__global__ __launch_bounds__(256)
void fused_w1_kernel(const float* __restrict__ W1,
                     const __nv_bfloat16* __restrict__ n1hi,
                     const __nv_bfloat16* __restrict__ n1lo,
                     const __nv_bfloat16* __restrict__ n0hi,
                     const __nv_bfloat16* __restrict__ n0lo,
                     const float* __restrict__ Wx,
                     float* __restrict__ g1,
                     __nv_bfloat16* __restrict__ g03,
                     float scale)
{
    __shared__ __align__(16) __nv_bfloat16 tH[HCHUNK][DSLICE + 8];
    __shared__ __align__(16) __nv_bfloat16 tL[HCHUNK][DSLICE + 8];
    __shared__ float g1buf[HCHUNK][17];

    const int t = threadIdx.x, lane = t & 31, wid = t >> 5;
    const long d0 = (long)blockIdx.x * DSLICE;

    uint4 pre[8];

    auto issue_loads = [&](int hc) {
#pragma unroll
        for (int i = 0; i < 8; ++i) {
            int f = t + i * 256;
            int row = f >> 6, c4 = f & 63;
            long d = d0 + (long)c4 * 4;
            if (d + 4 <= DD)
                pre[i] = *(const uint4*)(W1 + (long)(hc * HCHUNK + row) * DD + d);
            else
                pre[i] = make_uint4(0, 0, 0, 0);
        }
    };
    auto store_tiles = [&]() {
#pragma unroll
        for (int i = 0; i < 8; ++i) {
            int f = t + i * 256;
            int row = f >> 6, c4 = f & 63;
            float4 v = *(float4*)&pre[i];
            __nv_bfloat16 hh[4], ll[4];
            split_bf16(v.x, hh[0], ll[0]);
            split_bf16(v.y, hh[1], ll[1]);
            split_bf16(v.z, hh[2], ll[2]);
            split_bf16(v.w, hh[3], ll[3]);
            *(uint2*)&tH[row][c4 * 4] = *(uint2*)hh;
            *(uint2*)&tL[row][c4 * 4] = *(uint2*)ll;
        }
    };

    float accg0[8][4] = {};

    issue_loads(0);
    store_tiles();
    for (int i = t; i < HCHUNK * 17; i += 256) ((float*)g1buf)[i] = 0.f;
    __syncthreads();

    for (int hc = 0; hc < NCHUNK; ++hc) {
        if (hc + 1 < NCHUNK) issue_loads(hc + 1);

        if (wid < 4) {
            const int tr_r = lane & 15, tr_c = (lane >> 4) * 8;
            const int ar = lane >> 2, ac = (lane & 3) * 2;
#pragma unroll
            for (int ks = 0; ks < 2; ++ks) {
                int kb = hc * HCHUNK + ks * 16;
                uint32_t ah[4], al[4];
                ah[0] = *(const uint32_t*)(n1hi + ar * HH + kb + ac);
                ah[1] = *(const uint32_t*)(n1hi + (ar + 8) * HH + kb + ac);
                ah[2] = *(const uint32_t*)(n1hi + ar * HH + kb + ac + 8);
                ah[3] = *(const uint32_t*)(n1hi + (ar + 8) * HH + kb + ac + 8);
                al[0] = *(const uint32_t*)(n1lo + ar * HH + kb + ac);
                al[1] = *(const uint32_t*)(n1lo + (ar + 8) * HH + kb + ac);
                al[2] = *(const uint32_t*)(n1lo + ar * HH + kb + ac + 8);
                al[3] = *(const uint32_t*)(n1lo + (ar + 8) * HH + kb + ac + 8);
#pragma unroll
                for (int q = 0; q < 4; ++q) {
                    uint32_t bh[4], bl[4];
                    ldm_x4_t(bh, smem_u32(&tH[ks * 16 + tr_r][wid * 64 + q * 16 + tr_c]));
                    ldm_x4_t(bl, smem_u32(&tL[ks * 16 + tr_r][wid * 64 + q * 16 + tr_c]));
                    mma16816(accg0[q * 2],     ah, &bh[0]);
                    mma16816(accg0[q * 2],     al, &bh[0]);
                    mma16816(accg0[q * 2],     ah, &bl[0]);
                    mma16816(accg0[q * 2 + 1], ah, &bh[2]);
                    mma16816(accg0[q * 2 + 1], al, &bh[2]);
                    mma16816(accg0[q * 2 + 1], ah, &bl[2]);
                }
            }
        } else {
            const int w = wid - 4;
            const int a_r = lane & 15, a_c = (lane >> 4) * 8;
            float acc1[2][2][4] = {};
#pragma unroll
            for (int ks = 0; ks < 4; ++ks) {
                long dk = d0 + w * 64 + ks * 16;
                uint32_t bh[2][2], bl[2][2];
#pragma unroll
                for (int nt = 0; nt < 2; ++nt) {
                    long baddr = (long)(nt * 8 + (lane >> 2)) * DD + dk + (lane & 3) * 2;
                    bh[nt][0] = *(const uint32_t*)(n0hi + baddr);
                    bh[nt][1] = *(const uint32_t*)(n0hi + baddr + 8);
                    bl[nt][0] = *(const uint32_t*)(n0lo + baddr);
                    bl[nt][1] = *(const uint32_t*)(n0lo + baddr + 8);
                }
#pragma unroll
                for (int mt = 0; mt < 2; ++mt) {
                    uint32_t ahf[4], alf[4];
                    ldm_x4(ahf, smem_u32(&tH[mt * 16 + a_r][w * 64 + ks * 16 + a_c]));
                    ldm_x4(alf, smem_u32(&tL[mt * 16 + a_r][w * 64 + ks * 16 + a_c]));
#pragma unroll
                    for (int nt = 0; nt < 2; ++nt) {
                        mma16816(acc1[mt][nt], ahf, bh[nt]);
                        mma16816(acc1[mt][nt], alf, bh[nt]);
                        mma16816(acc1[mt][nt], ahf, bl[nt]);
                    }
                }
            }
            const int cr = lane >> 2, cc = (lane & 3) * 2;
#pragma unroll
            for (int mt = 0; mt < 2; ++mt)
#pragma unroll
                for (int nt = 0; nt < 2; ++nt) {
                    atomicAdd(&g1buf[mt * 16 + cr][nt * 8 + cc],         acc1[mt][nt][0]);
                    atomicAdd(&g1buf[mt * 16 + cr][nt * 8 + cc + 1],     acc1[mt][nt][1]);
                    atomicAdd(&g1buf[mt * 16 + cr + 8][nt * 8 + cc],     acc1[mt][nt][2]);
                    atomicAdd(&g1buf[mt * 16 + cr + 8][nt * 8 + cc + 1], acc1[mt][nt][3]);
                }
        }
        __syncthreads();

#pragma unroll
        for (int i = 0; i < 2; ++i) {
            int idx = t + i * 256;
            int h = idx >> 4, b = idx & 15;
            float v = g1buf[h][b];
            if (v != 0.f) atomicAdd(&g1[b * HH + hc * HCHUNK + h], v);
            g1buf[h][b] = 0.f;
        }
        if (hc + 1 < NCHUNK) store_tiles();
        __syncthreads();
    }

    if (wid < 4) {
        const int ar = lane >> 2, cc = (lane & 3) * 2;
#pragma unroll
        for (int q = 0; q < 8; ++q) {
            int dn = wid * 64 + q * 8 + cc;
            long d = d0 + dn;
            if (d + 1 < DD) {
                int s = (int)(d / EE), e = (int)(d % EE);
#pragma unroll
                for (int half = 0; half < 2; ++half) {
                    int bb = ar + half * 8;
                    float2 wx = *(const float2*)(Wx + (long)bb * DD + d);
                    float v0 = (wx.x + accg0[q][half * 2])     * scale;
                    float v1 = (wx.y + accg0[q][half * 2 + 1]) * scale;
                    __nv_bfloat16 hi[2], lo[2];
                    split_bf16(v0, hi[0], lo[0]);
                    split_bf16(v1, hi[1], lo[1]);
                    __nv_bfloat16* o = g03 + ((long)(bb * SS + s)) * KA3;
                    *(uint32_t*)&o[e]       = *(uint32_t*)hi;
                    *(uint32_t*)&o[320 + e] = *(uint32_t*)lo;
                    *(uint32_t*)&o[640 + e] = *(uint32_t*)hi;
                }
            }
        }
    }
}

// ---------------- pipelined HMMA GEMM: C = A3 · B3^T -------------------------
// cp.async double-buffered, K-stage 32. 2 CTAs/SM via launch_bounds.
// kchunks counts 32-wide K stages.
__global__ __launch_bounds__(256, 2)
void hmma_gemm_kernel(const __nv_bfloat16* __restrict__ A3,
                      const __nv_bfloat16* __restrict__ B3,
                      float* __restrict__ C,
                      __nv_bfloat16* __restrict__ Chi,
                      __nv_bfloat16* __restrict__ Clo,
                      int ldA, long bsA, int rowsA,
                      int ldB, long bsB, int rowsB,
                      int ldC, long bsC, int Mvalid, int Nvalid,
                      int kchunks)
{
    __shared__ __align__(16) __nv_bfloat16 As[2][128][40];
    __shared__ __align__(16) __nv_bfloat16 Bs[2][128][40];
    const int t = threadIdx.x, lane = t & 31, wid = t >> 5;
    const int wm = wid >> 2, wn = wid & 3;
    const int b = blockIdx.z, m0 = blockIdx.y * 128, n0 = blockIdx.x * 128;
    const __nv_bfloat16* Ab = A3 + (long)b * bsA;
    const __nv_bfloat16* Bb = B3 + (long)b * bsB;
    float acc[4][4][4] = {};

    // stage loader: 128 rows x 32 cols bf16 per matrix; 2 x 16B per thread per matrix
    const int l_row = t >> 2, l_q = t & 3;      // rows 0..63 (and +64)
    auto stage_in = [&](int ch, int buf) {
        long kg = (long)ch * 32 + l_q * 8;
#pragma unroll
        for (int i = 0; i < 2; ++i) {
            int row = l_row + i * 64;
            int ra = m0 + row, rb = n0 + row;
            int ca = (ra < rowsA) ? 16 : 0;
            int cb = (rb < rowsB) ? 16 : 0;
            if (ra >= rowsA) ra = 0;
            if (rb >= rowsB) rb = 0;
            cp_async16(smem_u32(&As[buf][row][l_q * 8]), Ab + (long)ra * ldA + kg, ca);
            cp_async16(smem_u32(&Bs[buf][row][l_q * 8]), Bb + (long)rb * ldB + kg, cb);
        }
    };

    stage_in(0, 0); cp_commit();
    if (kchunks > 1) { stage_in(1, 1); }
    cp_commit();

    const int a_lm = lane & 15;
    const int a_lk = (lane >> 4) * 8;
    const int b_ln = (lane & 7) + ((lane >> 4) & 1) * 8;
    const int b_lk = ((lane >> 3) & 1) * 8;

    for (int ch = 0; ch < kchunks; ++ch) {
        const int buf = ch & 1;
        cp_wait<1>();
        __syncthreads();
#pragma unroll
        for (int ks = 0; ks < 2; ++ks) {
            uint32_t af[4][4], bf[4][2];
#pragma unroll
            for (int mf = 0; mf < 4; ++mf)
                ldm_x4(af[mf], smem_u32(&As[buf][wm * 64 + mf * 16 + a_lm][ks * 16 + a_lk]));
#pragma unroll
            for (int nf2 = 0; nf2 < 2; ++nf2) {
                uint32_t r[4];
                ldm_x4(r, smem_u32(&Bs[buf][wn * 32 + nf2 * 16 + b_ln][ks * 16 + b_lk]));
                bf[nf2 * 2][0] = r[0];     bf[nf2 * 2][1] = r[1];
                bf[nf2 * 2 + 1][0] = r[2]; bf[nf2 * 2 + 1][1] = r[3];
            }
#pragma unroll
            for (int mf = 0; mf < 4; ++mf)
#pragma unroll
                for (int nf = 0; nf < 4; ++nf)
                    mma16816(acc[mf][nf], af[mf], bf[nf]);
        }
        __syncthreads();
        if (ch + 2 < kchunks) stage_in(ch + 2, buf);
        cp_commit();
    }

    float* Cb = C + (long)b * bsC;
    const int mbase = m0 + wm * 64, nbase = n0 + wn * 32;
#pragma unroll
    for (int mf = 0; mf < 4; ++mf) {
#pragma unroll
        for (int nf = 0; nf < 4; ++nf) {
            int m = mbase + mf * 16 + (lane >> 2);
            int n = nbase + nf * 8 + (lane & 3) * 2;
            if (n < Nvalid) {
#pragma unroll
                for (int half = 0; half < 2; ++half) {
                    int mm = m + half * 8;
                    float v0 = acc[mf][nf][half * 2], v1 = acc[mf][nf][half * 2 + 1];
                    if (mm < Mvalid) {
                        long o = (long)mm * ldC + n;
                        *(float2*)&Cb[o] = make_float2(v0, v1);
                        if (Chi) {
                            __nv_bfloat16 h0, l0, h1, l1;
                            split_bf16(v0, h0, l0);
                            split_bf16(v1, h1, l1);
                            __nv_bfloat162 hh; hh.x = h0; hh.y = h1;
                            __nv_bfloat162 ll; ll.x = l0; ll.y = l1;
                            *(__nv_bfloat162*)&Chi[(long)b * bsC + o] = hh;
                            *(__nv_bfloat162*)&Clo[(long)b * bsC + o] = ll;
                        }
                    }
                }
            }
        }
    }
}

// ---------------- conversions -------------------------------------------------
__global__ void conv_x_kernel(const float* __restrict__ x,
                              __nv_bfloat16* __restrict__ x3,
                              __nv_bfloat16* __restrict__ xT3,
                              __nv_bfloat16* __restrict__ xA3)
{
    int s = blockIdx.x, b = blockIdx.y, e = threadIdx.x;
    __nv_bfloat16 zero = __float2bfloat16(0.f);
    if (s < SS) {
        float v = (e < EE) ? x[((long)b * SS + s) * EE + e] : 0.f;
        __nv_bfloat16 hi, lo;
        split_bf16(v, hi, lo);
        __nv_bfloat16* xr = x3 + ((long)b * SS + s) * KA3;
        xr[e] = hi; xr[320 + e] = hi; xr[640 + e] = lo;
        __nv_bfloat16* xa = xA3 + ((long)b * SS + s) * KA3;
        xa[e] = hi; xa[320 + e] = lo; xa[640 + e] = hi;
        __nv_bfloat16* tr = xT3 + ((long)b * 320 + e) * KP3;
        tr[s] = hi; tr[640 + s] = hi; tr[1280 + s] = lo;
    } else {
        __nv_bfloat16* tr = xT3 + ((long)b * 320 + e) * KP3;
        tr[s] = zero; tr[640 + s] = zero; tr[1280 + s] = zero;
    }
}

__global__ void conv_w0_kernel(const float* __restrict__ W0,
                               __nv_bfloat16* __restrict__ W03)
{
    int f = blockIdx.x, e = threadIdx.x;
    float v = (e < EE) ? W0[f * EE + e] : 0.f;
    __nv_bfloat16 hi, lo;
    split_bf16(v, hi, lo);
    __nv_bfloat16* row = W03 + (long)f * KA3;
    row[e] = hi; row[320 + e] = hi; row[640 + e] = lo;
}

__global__ void conv_wx_kernel(const float* __restrict__ Wx,
                               __nv_bfloat16* __restrict__ g03, float scale)
{
    long r = blockIdx.x;
    int e = threadIdx.x;
    float v = (e < EE) ? scale * Wx[r * EE + e] : 0.f;
    __nv_bfloat16 hi, lo;
    split_bf16(v, hi, lo);
    __nv_bfloat16* out = g03 + r * KA3;
    out[e] = hi; out[320 + e] = lo; out[640 + e] = hi;
}

// ---------------- small kernels ----------------------------------------------
__global__ void init_g1_kernel(const float* __restrict__ b1, const float* __restrict__ n2,
                               const float* __restrict__ W2, float* __restrict__ g1)
{
    int b = blockIdx.x, h = threadIdx.x;
    g1[b * HH + h] = b1[h] + n2[b * NCC] * W2[h] + n2[b * NCC + 1] * W2[HH + h];
}

__global__ void g2_kernel(const float* __restrict__ n1, const float* __restrict__ W2,
                          const float* __restrict__ b2, float* __restrict__ n2n)
{
    int t = threadIdx.x;
    int wid = t >> 5, lane = t & 31;
    int b = wid >> 1, c = wid & 1;
    float s = 0.f;
    for (int h = lane; h < HH; h += 32)
        s += n1[b * HH + h] * W2[c * HH + h];
#pragma unroll
    for (int off = 16; off > 0; off >>= 1)
        s += __shfl_down_sync(0xffffffffu, s, off);
    if (lane == 0) n2n[b * NCC + c] = tanhf(b2[c] + s);
}

__global__ void tanh_n1_kernel(const float* __restrict__ g1, float* __restrict__ n1n,
                               __nv_bfloat16* __restrict__ n1hi,
                               __nv_bfloat16* __restrict__ n1lo)
{
    int i = blockIdx.x * blockDim.x + threadIdx.x;
    float v = tanhf(g1[i]);
    n1n[i] = v;
    __nv_bfloat16 hi, lo;
    split_bf16(v, hi, lo);
    n1hi[i] = hi; n1lo[i] = lo;
}

__global__ void init_step0_kernel(const float* __restrict__ b1, const float* __restrict__ b2,
                                  float* __restrict__ n1n, float* __restrict__ n2n,
                                  __nv_bfloat16* __restrict__ n1hi,
                                  __nv_bfloat16* __restrict__ n1lo)
{
    int b = blockIdx.x, h = threadIdx.x;
    float v = tanhf(b1[h]);
    n1n[b * HH + h] = v;
    __nv_bfloat16 hi, lo;
    split_bf16(v, hi, lo);
    n1hi[b * HH + h] = hi; n1lo[b * HH + h] = lo;
    if (h < NCC) n2n[b * NCC + h] = tanhf(b2[h]);
}

// ---------------- softmax + convert to P3 triple (hi|lo|hi) ------------------
__global__ __launch_bounds__(256)
void softmax_conv_kernel(const float* __restrict__ Praw, __nv_bfloat16* __restrict__ P3)
{
    __shared__ float red[256];
    long r = blockIdx.x;
    const float* p = Praw + r * SS;
    __nv_bfloat16* out = P3 + r * KP3;
    int t = threadIdx.x;

    float a0 = (t < SS)       ? p[t]       : -INFINITY;
    float a1 = (t + 256 < SS) ? p[t + 256] : -INFINITY;
    float a2 = (t + 512 < SS) ? p[t + 512] : -INFINITY;

    float mx = fmaxf(a0, fmaxf(a1, a2));
    red[t] = mx; __syncthreads();
    for (int s = 128; s > 0; s >>= 1) {
        if (t < s) red[t] = fmaxf(red[t], red[t + s]);
        __syncthreads();
    }
    mx = red[0]; __syncthreads();

    float e0 = (t < SS)       ? expf(a0 - mx) : 0.f;
    float e1 = (t + 256 < SS) ? expf(a1 - mx) : 0.f;
    float e2 = (t + 512 < SS) ? expf(a2 - mx) : 0.f;
    red[t] = e0 + e1 + e2; __syncthreads();
    for (int s = 128; s > 0; s >>= 1) {
        if (t < s) red[t] += red[t + s];
        __syncthreads();
    }
    float inv = 1.f / red[0];

    __nv_bfloat16 zero = __float2bfloat16(0.f);
    for (int k = 0; k < 3; ++k) {
        int i = t + k * 256;
        if (i >= 640) break;
        if (i < SS) {
            float v = (k == 0 ? e0 : (k == 1 ? e1 : e2)) * inv;
            __nv_bfloat16 hi, lo;
            split_bf16(v, hi, lo);
            out[i] = hi; out[640 + i] = lo; out[1280 + i] = hi;
        } else {
            out[i] = zero; out[640 + i] = zero; out[1280 + i] = zero;
        }
    }
}

// ---------------- host driver ------------------------------------------------
static float* sym_addr_f(const void* sym)
{
    void* p = nullptr;
    cudaGetSymbolAddress(&p, sym);
    return (float*)p;
}
static __nv_bfloat16* sym_addr_b(const void* sym)
{
    void* p = nullptr;
    cudaGetSymbolAddress(&p, sym);
    return (__nv_bfloat16*)p;
}

extern "C" void kernel_launch(void* const* d_in, const int* in_sizes, int n_in,
                              void* d_out, int out_size)
{
    const float* x   = (const float*)d_in[0];
    const float* W0  = (const float*)d_in[5];
    const float* W1  = (const float*)d_in[6];
    const float* b1  = (const float*)d_in[7];
    const float* W2  = (const float*)d_in[8];
    const float* b2  = (const float*)d_in[9];
    float* out = (float*)d_out;

    float* Wx   = sym_addr_f(g_Wx);
    float* Praw = sym_addr_f(g_Praw);
    float* g1   = sym_addr_f(g_g1);
    float* n0buf[2] = { sym_addr_f(g_n0a), sym_addr_f(g_n0b) };
    float* n1buf[2] = { sym_addr_f(g_n1a), sym_addr_f(g_n1b) };
    float* n2buf[2] = { sym_addr_f(g_n2a), sym_addr_f(g_n2b) };
    __nv_bfloat16* g03  = sym_addr_b(g_g03);
    __nv_bfloat16* x3   = sym_addr_b(g_x3);
    __nv_bfloat16* P3   = sym_addr_b(g_P3);
    __nv_bfloat16* xT3  = sym_addr_b(g_xT3);
    __nv_bfloat16* xA3  = sym_addr_b(g_xA3);
    __nv_bfloat16* W03  = sym_addr_b(g_W03);
    __nv_bfloat16* n0hi = sym_addr_b(g_n0hi);
    __nv_bfloat16* n0lo = sym_addr_b(g_n0lo);
    __nv_bfloat16* n1hi = sym_addr_b(g_n1hi);
    __nv_bfloat16* n1lo = sym_addr_b(g_n1lo);

    const float scale = 1.0f / sqrtf((float)EE);

    // one-time conversions
    {
        dim3 g(640, BB);
        conv_x_kernel<<<g, 320>>>(x, x3, xT3, xA3);
    }
    conv_w0_kernel<<<EE, 320>>>(W0, W03);

    // Wx = x @ W0^T via HMMA (M=9600, N=300, K3=960 -> 30 stages)
    {
        dim3 grid(3, 75, 1);
        hmma_gemm_kernel<<<grid, 256>>>(
            xA3, W03, Wx, nullptr, nullptr,
            KA3, 0, BB * SS,
            KA3, 0, EE,
            EE, 0, BB * SS, EE,
            30);
    }

    const float* n0c = nullptr;
    const float* n1c = nullptr;
    const float* n2c = nullptr;

    for (int step = 0; step < TT; ++step) {
        float* n0n = n0buf[step & 1];
        float* n1n = n1buf[step & 1];
        float* n2n = n2buf[step & 1];

        if (step == 0) {
            init_step0_kernel<<<BB, HH>>>(b1, b2, n1n, n2n, n1hi, n1lo);
            conv_wx_kernel<<<BB * SS, 320>>>(Wx, g03, scale);
        } else {
            init_g1_kernel<<<BB, HH>>>(b1, n2c, W2, g1);
            g2_kernel<<<1, 1024>>>(n1c, W2, b2, n2n);
            fused_w1_kernel<<<NDBLK, 256>>>(W1, n1hi, n1lo, n0hi, n0lo,
                                            Wx, g1, g03, scale);
            tanh_n1_kernel<<<BB, HH>>>(g1, n1n, n1hi, n1lo);
        }

        // scores = (scale*g0) @ x^T  [pipelined HMMA, 30 stages]
        {
            dim3 grid(5, 5, BB);
            hmma_gemm_kernel<<<grid, 256>>>(
                g03, x3, Praw, nullptr, nullptr,
                KA3, (long)SS * KA3, SS,
                KA3, (long)SS * KA3, SS,
                SS, (long)SS * SS, SS, SS,
                30);
        }
        softmax_conv_kernel<<<BB * SS, 256>>>(Praw, P3);
        // n0n = P @ x  [pipelined HMMA, 60 stages]
        {
            dim3 grid(3, 5, BB);
            hmma_gemm_kernel<<<grid, 256>>>(
                P3, xT3, n0n, n0hi, n0lo,
                KP3, (long)SS * KP3, SS,
                KP3, (long)320 * KP3, 320,
                EE, (long)SS * EE, SS, EE,
                60);
        }

        n0c = n0n; n1c = n1n; n2c = n2n;
    }

    // pack output: n0 | n1 | n2
    cudaMemcpyAsync(out, n0c, (size_t)BB * SS * EE * sizeof(float),
                    cudaMemcpyDeviceToDevice, 0);
    cudaMemcpyAsync(out + (long)BB * SS * EE, n1c, (size_t)BB * HH * sizeof(float),
                    cudaMemcpyDeviceToDevice, 0);
    cudaMemcpyAsync(out + (long)BB * SS * EE + BB * HH, n2c,
                    (size_t)BB * NCC * sizeof(float), cudaMemcpyDeviceToDevice, 0);
}

// round 8
// speedup vs baseline: 3.6286x; 1.6885x over previous
#include <cuda_runtime.h>
#include <cuda_fp16.h>
#include <math.h>
#include <stdint.h>

// Problem constants
#define BB   16
#define SS   600
#define EE   300
#define HH   512
#define NCC  2
#define DD   180000L
#define TT   3

#define KAH  320    // padded K for e-dim (300 -> 320)
#define KPH  640    // padded K for s-dim (600 -> 640)

// fused W1 kernel tiling
#define DSLICE 256
#define HCHUNK 32
#define NCHUNK (HH / HCHUNK)
#define NDBLK  ((int)((DD + DSLICE - 1) / DSLICE))

// ---------------- scratch (device globals) -----------------------------------
__device__ float g_Wx [BB * SS * EE];
__device__ float g_Praw[BB * SS * SS];
__device__ float g_n0a[BB * SS * EE];
__device__ float g_n0b[BB * SS * EE];
__device__ float g_n1a[BB * HH];
__device__ float g_n1b[BB * HH];
__device__ float g_n2a[BB * NCC];
__device__ float g_n2b[BB * NCC];
__device__ float g_g1 [BB * HH];
__device__ __half g_xh  [(size_t)BB * SS * KAH];   // B of scores / A of Wx
__device__ __half g_xTh [(size_t)BB * 320 * KPH];  // B of PV
__device__ __half g_g0h [(size_t)BB * SS * KAH];   // A of scores (scaled g0)
__device__ __half g_Ph  [(size_t)BB * SS * KPH];   // A of PV
__device__ __half g_W0h [(size_t)EE * KAH];        // B of Wx
__device__ __half g_n0h [(size_t)BB * DD + 512];   // fp16 n0 (g1 operand)
__device__ __half g_n1h [BB * HH];                 // fp16 n1 (g0 operand)

// ---------------- helpers -----------------------------------------------------
__device__ __forceinline__ uint32_t smem_u32(const void* p) {
    uint32_t a;
    asm("{ .reg .u64 t; cvta.to.shared.u64 t, %1; cvt.u32.u64 %0, t; }" : "=r"(a) : "l"(p));
    return a;
}
__device__ __forceinline__ void ldm_x4(uint32_t* r, uint32_t addr) {
    asm volatile("ldmatrix.sync.aligned.m8n8.x4.shared.b16 {%0,%1,%2,%3}, [%4];"
                 : "=r"(r[0]), "=r"(r[1]), "=r"(r[2]), "=r"(r[3]) : "r"(addr));
}
__device__ __forceinline__ void ldm_x4_t(uint32_t* r, uint32_t addr) {
    asm volatile("ldmatrix.sync.aligned.m8n8.x4.trans.shared.b16 {%0,%1,%2,%3}, [%4];"
                 : "=r"(r[0]), "=r"(r[1]), "=r"(r[2]), "=r"(r[3]) : "r"(addr));
}
__device__ __forceinline__ void mma16816(float* c, const uint32_t* a, const uint32_t* b) {
    asm volatile(
        "mma.sync.aligned.m16n8k16.row.col.f32.f16.f16.f32 "
        "{%0,%1,%2,%3}, {%4,%5,%6,%7}, {%8,%9}, {%0,%1,%2,%3};"
        : "+f"(c[0]), "+f"(c[1]), "+f"(c[2]), "+f"(c[3])
        : "r"(a[0]), "r"(a[1]), "r"(a[2]), "r"(a[3]), "r"(b[0]), "r"(b[1]));
}
__device__ __forceinline__ void cp_async16(uint32_t dst, const void* src, int bytes) {
    asm volatile("cp.async.cg.shared.global [%0], [%1], 16, %2;"
                 :: "r"(dst), "l"(src), "r"(bytes));
}
__device__ __forceinline__ void cp_commit() {
    asm volatile("cp.async.commit_group;");
}
template <int N>
__device__ __forceinline__ void cp_wait() {
    asm volatile("cp.async.wait_group %0;" :: "n"(N));
}

// ============ fused per-step W1 kernel (fp16 single-term) ====================
// Streams W1 (fp32) ONCE per step; computes
//   g0h <- fp16((Wx + n1 @ W1) * scale)
//   g1  += n0flat @ W1^T   (fp32 atomics)
__global__ __launch_bounds__(256)
void fused_w1_kernel(const float* __restrict__ W1,
                     const __half* __restrict__ n1h,
                     const __half* __restrict__ n0h,
                     const float* __restrict__ Wx,
                     float* __restrict__ g1,
                     __half* __restrict__ g0h,
                     float scale)
{
    __shared__ __align__(16) __half tF[HCHUNK][DSLICE + 8];
    __shared__ float g1buf[HCHUNK][17];

    const int t = threadIdx.x, lane = t & 31, wid = t >> 5;
    const long d0 = (long)blockIdx.x * DSLICE;

    uint4 pre[8];

    auto issue_loads = [&](int hc) {
#pragma unroll
        for (int i = 0; i < 8; ++i) {
            int f = t + i * 256;
            int row = f >> 6, c4 = f & 63;
            long d = d0 + (long)c4 * 4;
            if (d + 4 <= DD)
                pre[i] = *(const uint4*)(W1 + (long)(hc * HCHUNK + row) * DD + d);
            else
                pre[i] = make_uint4(0, 0, 0, 0);
        }
    };
    auto store_tiles = [&]() {
#pragma unroll
        for (int i = 0; i < 8; ++i) {
            int f = t + i * 256;
            int row = f >> 6, c4 = f & 63;
            float4 v = *(float4*)&pre[i];
            __half h[4];
            h[0] = __float2half_rn(v.x);
            h[1] = __float2half_rn(v.y);
            h[2] = __float2half_rn(v.z);
            h[3] = __float2half_rn(v.w);
            *(uint2*)&tF[row][c4 * 4] = *(uint2*)h;
        }
    };

    float accg0[8][4] = {};

    issue_loads(0);
    store_tiles();
    for (int i = t; i < HCHUNK * 17; i += 256) ((float*)g1buf)[i] = 0.f;
    __syncthreads();

    for (int hc = 0; hc < NCHUNK; ++hc) {
        if (hc + 1 < NCHUNK) issue_loads(hc + 1);

        if (wid < 4) {
            // g0: M=16 batch, N=64 d-cols per warp, K=32 h
            const int tr_r = lane & 15, tr_c = (lane >> 4) * 8;
            const int ar = lane >> 2, ac = (lane & 3) * 2;
#pragma unroll
            for (int ks = 0; ks < 2; ++ks) {
                int kb = hc * HCHUNK + ks * 16;
                uint32_t ah[4];
                ah[0] = *(const uint32_t*)(n1h + ar * HH + kb + ac);
                ah[1] = *(const uint32_t*)(n1h + (ar + 8) * HH + kb + ac);
                ah[2] = *(const uint32_t*)(n1h + ar * HH + kb + ac + 8);
                ah[3] = *(const uint32_t*)(n1h + (ar + 8) * HH + kb + ac + 8);
#pragma unroll
                for (int q = 0; q < 4; ++q) {
                    uint32_t bf[4];
                    ldm_x4_t(bf, smem_u32(&tF[ks * 16 + tr_r][wid * 64 + q * 16 + tr_c]));
                    mma16816(accg0[q * 2],     ah, &bf[0]);
                    mma16816(accg0[q * 2 + 1], ah, &bf[2]);
                }
            }
        } else {
            // g1: M=32 h, N=16 batch, K=64 d-slice per warp
            const int w = wid - 4;
            const int a_r = lane & 15, a_c = (lane >> 4) * 8;
            float acc1[2][2][4] = {};
#pragma unroll
            for (int ks = 0; ks < 4; ++ks) {
                long dk = d0 + w * 64 + ks * 16;
                uint32_t bh[2][2];
#pragma unroll
                for (int nt = 0; nt < 2; ++nt) {
                    long baddr = (long)(nt * 8 + (lane >> 2)) * DD + dk + (lane & 3) * 2;
                    bh[nt][0] = *(const uint32_t*)(n0h + baddr);
                    bh[nt][1] = *(const uint32_t*)(n0h + baddr + 8);
                }
#pragma unroll
                for (int mt = 0; mt < 2; ++mt) {
                    uint32_t af[4];
                    ldm_x4(af, smem_u32(&tF[mt * 16 + a_r][w * 64 + ks * 16 + a_c]));
#pragma unroll
                    for (int nt = 0; nt < 2; ++nt)
                        mma16816(acc1[mt][nt], af, bh[nt]);
                }
            }
            const int cr = lane >> 2, cc = (lane & 3) * 2;
#pragma unroll
            for (int mt = 0; mt < 2; ++mt)
#pragma unroll
                for (int nt = 0; nt < 2; ++nt) {
                    atomicAdd(&g1buf[mt * 16 + cr][nt * 8 + cc],         acc1[mt][nt][0]);
                    atomicAdd(&g1buf[mt * 16 + cr][nt * 8 + cc + 1],     acc1[mt][nt][1]);
                    atomicAdd(&g1buf[mt * 16 + cr + 8][nt * 8 + cc],     acc1[mt][nt][2]);
                    atomicAdd(&g1buf[mt * 16 + cr + 8][nt * 8 + cc + 1], acc1[mt][nt][3]);
                }
        }
        __syncthreads();

#pragma unroll
        for (int i = 0; i < 2; ++i) {
            int idx = t + i * 256;
            int h = idx >> 4, b = idx & 15;
            float v = g1buf[h][b];
            if (v != 0.f) atomicAdd(&g1[b * HH + hc * HCHUNK + h], v);
            g1buf[h][b] = 0.f;
        }
        if (hc + 1 < NCHUNK) store_tiles();
        __syncthreads();
    }

    // g0 epilogue: (Wx + acc) * scale -> fp16 at [b*SS+s][KAH]
    if (wid < 4) {
        const int ar = lane >> 2, cc = (lane & 3) * 2;
#pragma unroll
        for (int q = 0; q < 8; ++q) {
            int dn = wid * 64 + q * 8 + cc;
            long d = d0 + dn;
            if (d + 1 < DD) {
                int s = (int)(d / EE), e = (int)(d % EE);
#pragma unroll
                for (int half = 0; half < 2; ++half) {
                    int bb = ar + half * 8;
                    float2 wx = *(const float2*)(Wx + (long)bb * DD + d);
                    __half h[2];
                    h[0] = __float2half_rn((wx.x + accg0[q][half * 2])     * scale);
                    h[1] = __float2half_rn((wx.y + accg0[q][half * 2 + 1]) * scale);
                    *(uint32_t*)&g0h[((long)(bb * SS + s)) * KAH + e] = *(uint32_t*)h;
                }
            }
        }
    }
}

// ---------------- pipelined HMMA GEMM (fp16): C = A · B^T --------------------
__global__ __launch_bounds__(256, 2)
void hmma_gemm_kernel(const __half* __restrict__ A,
                      const __half* __restrict__ B,
                      float* __restrict__ C,
                      __half* __restrict__ Ch,
                      int ldA, long bsA, int rowsA,
                      int ldB, long bsB, int rowsB,
                      int ldC, long bsC, int Mvalid, int Nvalid,
                      int kchunks)
{
    __shared__ __align__(16) __half As[2][128][40];
    __shared__ __align__(16) __half Bs[2][128][40];
    const int t = threadIdx.x, lane = t & 31, wid = t >> 5;
    const int wm = wid >> 2, wn = wid & 3;
    const int b = blockIdx.z, m0 = blockIdx.y * 128, n0 = blockIdx.x * 128;
    const __half* Ab = A + (long)b * bsA;
    const __half* Bb = B + (long)b * bsB;
    float acc[4][4][4] = {};

    const int l_row = t >> 2, l_q = t & 3;
    auto stage_in = [&](int ch, int buf) {
        long kg = (long)ch * 32 + l_q * 8;
#pragma unroll
        for (int i = 0; i < 2; ++i) {
            int row = l_row + i * 64;
            int ra = m0 + row, rb = n0 + row;
            int ca = (ra < rowsA) ? 16 : 0;
            int cb = (rb < rowsB) ? 16 : 0;
            if (ra >= rowsA) ra = 0;
            if (rb >= rowsB) rb = 0;
            cp_async16(smem_u32(&As[buf][row][l_q * 8]), Ab + (long)ra * ldA + kg, ca);
            cp_async16(smem_u32(&Bs[buf][row][l_q * 8]), Bb + (long)rb * ldB + kg, cb);
        }
    };

    stage_in(0, 0); cp_commit();
    if (kchunks > 1) { stage_in(1, 1); }
    cp_commit();

    const int a_lm = lane & 15;
    const int a_lk = (lane >> 4) * 8;
    const int b_ln = (lane & 7) + ((lane >> 4) & 1) * 8;
    const int b_lk = ((lane >> 3) & 1) * 8;

    for (int ch = 0; ch < kchunks; ++ch) {
        const int buf = ch & 1;
        cp_wait<1>();
        __syncthreads();
#pragma unroll
        for (int ks = 0; ks < 2; ++ks) {
            uint32_t af[4][4], bf[4][2];
#pragma unroll
            for (int mf = 0; mf < 4; ++mf)
                ldm_x4(af[mf], smem_u32(&As[buf][wm * 64 + mf * 16 + a_lm][ks * 16 + a_lk]));
#pragma unroll
            for (int nf2 = 0; nf2 < 2; ++nf2) {
                uint32_t r[4];
                ldm_x4(r, smem_u32(&Bs[buf][wn * 32 + nf2 * 16 + b_ln][ks * 16 + b_lk]));
                bf[nf2 * 2][0] = r[0];     bf[nf2 * 2][1] = r[1];
                bf[nf2 * 2 + 1][0] = r[2]; bf[nf2 * 2 + 1][1] = r[3];
            }
#pragma unroll
            for (int mf = 0; mf < 4; ++mf)
#pragma unroll
                for (int nf = 0; nf < 4; ++nf)
                    mma16816(acc[mf][nf], af[mf], bf[nf]);
        }
        __syncthreads();
        if (ch + 2 < kchunks) stage_in(ch + 2, buf);
        cp_commit();
    }

    float* Cb = C + (long)b * bsC;
    const int mbase = m0 + wm * 64, nbase = n0 + wn * 32;
#pragma unroll
    for (int mf = 0; mf < 4; ++mf) {
#pragma unroll
        for (int nf = 0; nf < 4; ++nf) {
            int m = mbase + mf * 16 + (lane >> 2);
            int n = nbase + nf * 8 + (lane & 3) * 2;
            if (n < Nvalid) {
#pragma unroll
                for (int half = 0; half < 2; ++half) {
                    int mm = m + half * 8;
                    float v0 = acc[mf][nf][half * 2], v1 = acc[mf][nf][half * 2 + 1];
                    if (mm < Mvalid) {
                        long o = (long)mm * ldC + n;
                        *(float2*)&Cb[o] = make_float2(v0, v1);
                        if (Ch) {
                            __half h[2];
                            h[0] = __float2half_rn(v0);
                            h[1] = __float2half_rn(v1);
                            *(uint32_t*)&Ch[(long)b * bsC + o] = *(uint32_t*)h;
                        }
                    }
                }
            }
        }
    }
}

// ---------------- conversions -------------------------------------------------
__global__ void conv_x_kernel(const float* __restrict__ x,
                              __half* __restrict__ xh,
                              __half* __restrict__ xTh)
{
    int s = blockIdx.x, b = blockIdx.y, e = threadIdx.x;
    if (s < SS) {
        float v = (e < EE) ? x[((long)b * SS + s) * EE + e] : 0.f;
        __half h = __float2half_rn(v);
        xh[((long)b * SS + s) * KAH + e] = h;
        xTh[((long)b * 320 + e) * KPH + s] = h;
    } else {
        xTh[((long)b * 320 + e) * KPH + s] = __float2half_rn(0.f);
    }
}

__global__ void conv_w0_kernel(const float* __restrict__ W0,
                               __half* __restrict__ W0h)
{
    int f = blockIdx.x, e = threadIdx.x;
    float v = (e < EE) ? W0[f * EE + e] : 0.f;
    W0h[(long)f * KAH + e] = __float2half_rn(v);
}

__global__ void conv_wx_kernel(const float* __restrict__ Wx,
                               __half* __restrict__ g0h, float scale)
{
    long r = blockIdx.x;
    int e = threadIdx.x;
    float v = (e < EE) ? scale * Wx[r * EE + e] : 0.f;
    g0h[r * KAH + e] = __float2half_rn(v);
}

// ---------------- small kernels ----------------------------------------------
__global__ void init_g1_kernel(const float* __restrict__ b1, const float* __restrict__ n2,
                               const float* __restrict__ W2, float* __restrict__ g1)
{
    int b = blockIdx.x, h = threadIdx.x;
    g1[b * HH + h] = b1[h] + n2[b * NCC] * W2[h] + n2[b * NCC + 1] * W2[HH + h];
}

__global__ void g2_kernel(const float* __restrict__ n1, const float* __restrict__ W2,
                          const float* __restrict__ b2, float* __restrict__ n2n)
{
    int t = threadIdx.x;
    int wid = t >> 5, lane = t & 31;
    int b = wid >> 1, c = wid & 1;
    float s = 0.f;
    for (int h = lane; h < HH; h += 32)
        s += n1[b * HH + h] * W2[c * HH + h];
#pragma unroll
    for (int off = 16; off > 0; off >>= 1)
        s += __shfl_down_sync(0xffffffffu, s, off);
    if (lane == 0) n2n[b * NCC + c] = tanhf(b2[c] + s);
}

__global__ void tanh_n1_kernel(const float* __restrict__ g1, float* __restrict__ n1n,
                               __half* __restrict__ n1h)
{
    int i = blockIdx.x * blockDim.x + threadIdx.x;
    float v = tanhf(g1[i]);
    n1n[i] = v;
    n1h[i] = __float2half_rn(v);
}

__global__ void init_step0_kernel(const float* __restrict__ b1, const float* __restrict__ b2,
                                  float* __restrict__ n1n, float* __restrict__ n2n,
                                  __half* __restrict__ n1h)
{
    int b = blockIdx.x, h = threadIdx.x;
    float v = tanhf(b1[h]);
    n1n[b * HH + h] = v;
    n1h[b * HH + h] = __float2half_rn(v);
    if (h < NCC) n2n[b * NCC + h] = tanhf(b2[h]);
}

// ---------------- softmax + convert to fp16 P --------------------------------
__global__ __launch_bounds__(256)
void softmax_conv_kernel(const float* __restrict__ Praw, __half* __restrict__ Ph)
{
    __shared__ float red[256];
    long r = blockIdx.x;
    const float* p = Praw + r * SS;
    __half* out = Ph + r * KPH;
    int t = threadIdx.x;

    float a0 = (t < SS)       ? p[t]       : -INFINITY;
    float a1 = (t + 256 < SS) ? p[t + 256] : -INFINITY;
    float a2 = (t + 512 < SS) ? p[t + 512] : -INFINITY;

    float mx = fmaxf(a0, fmaxf(a1, a2));
    red[t] = mx; __syncthreads();
    for (int s = 128; s > 0; s >>= 1) {
        if (t < s) red[t] = fmaxf(red[t], red[t + s]);
        __syncthreads();
    }
    mx = red[0]; __syncthreads();

    float e0 = (t < SS)       ? expf(a0 - mx) : 0.f;
    float e1 = (t + 256 < SS) ? expf(a1 - mx) : 0.f;
    float e2 = (t + 512 < SS) ? expf(a2 - mx) : 0.f;
    red[t] = e0 + e1 + e2; __syncthreads();
    for (int s = 128; s > 0; s >>= 1) {
        if (t < s) red[t] += red[t + s];
        __syncthreads();
    }
    float inv = 1.f / red[0];

    for (int k = 0; k < 3; ++k) {
        int i = t + k * 256;
        if (i >= KPH) break;
        float v = 0.f;
        if (i < SS) v = (k == 0 ? e0 : (k == 1 ? e1 : e2)) * inv;
        out[i] = __float2half_rn(v);
    }
}

// ---------------- host driver ------------------------------------------------
static float* sym_addr_f(const void* sym)
{
    void* p = nullptr;
    cudaGetSymbolAddress(&p, sym);
    return (float*)p;
}
static __half* sym_addr_h(const void* sym)
{
    void* p = nullptr;
    cudaGetSymbolAddress(&p, sym);
    return (__half*)p;
}

extern "C" void kernel_launch(void* const* d_in, const int* in_sizes, int n_in,
                              void* d_out, int out_size)
{
    const float* x   = (const float*)d_in[0];
    const float* W0  = (const float*)d_in[5];
    const float* W1  = (const float*)d_in[6];
    const float* b1  = (const float*)d_in[7];
    const float* W2  = (const float*)d_in[8];
    const float* b2  = (const float*)d_in[9];
    float* out = (float*)d_out;

    float* Wx   = sym_addr_f(g_Wx);
    float* Praw = sym_addr_f(g_Praw);
    float* g1   = sym_addr_f(g_g1);
    float* n0buf[2] = { sym_addr_f(g_n0a), sym_addr_f(g_n0b) };
    float* n1buf[2] = { sym_addr_f(g_n1a), sym_addr_f(g_n1b) };
    float* n2buf[2] = { sym_addr_f(g_n2a), sym_addr_f(g_n2b) };
    __half* xh   = sym_addr_h(g_xh);
    __half* xTh  = sym_addr_h(g_xTh);
    __half* g0h  = sym_addr_h(g_g0h);
    __half* Ph   = sym_addr_h(g_Ph);
    __half* W0h  = sym_addr_h(g_W0h);
    __half* n0h  = sym_addr_h(g_n0h);
    __half* n1h  = sym_addr_h(g_n1h);

    const float scale = 1.0f / sqrtf((float)EE);

    // one-time conversions
    {
        dim3 g(640, BB);
        conv_x_kernel<<<g, 320>>>(x, xh, xTh);
    }
    conv_w0_kernel<<<EE, 320>>>(W0, W0h);

    // Wx = x @ W0^T (fp16 HMMA, K=320 -> 10 stages)
    {
        dim3 grid(3, 75, 1);
        hmma_gemm_kernel<<<grid, 256>>>(
            xh, W0h, Wx, nullptr,
            KAH, 0, BB * SS,
            KAH, 0, EE,
            EE, 0, BB * SS, EE,
            10);
    }

    const float* n0c = nullptr;
    const float* n1c = nullptr;
    const float* n2c = nullptr;

    for (int step = 0; step < TT; ++step) {
        float* n0n = n0buf[step & 1];
        float* n1n = n1buf[step & 1];
        float* n2n = n2buf[step & 1];

        if (step == 0) {
            init_step0_kernel<<<BB, HH>>>(b1, b2, n1n, n2n, n1h);
            conv_wx_kernel<<<BB * SS, 320>>>(Wx, g0h, scale);
        } else {
            init_g1_kernel<<<BB, HH>>>(b1, n2c, W2, g1);
            g2_kernel<<<1, 1024>>>(n1c, W2, b2, n2n);
            fused_w1_kernel<<<NDBLK, 256>>>(W1, n1h, n0h, Wx, g1, g0h, scale);
            tanh_n1_kernel<<<BB, HH>>>(g1, n1n, n1h);
        }

        // scores = (scale*g0) @ x^T  (fp16 HMMA, K=320 -> 10 stages)
        {
            dim3 grid(5, 5, BB);
            hmma_gemm_kernel<<<grid, 256>>>(
                g0h, xh, Praw, nullptr,
                KAH, (long)SS * KAH, SS,
                KAH, (long)SS * KAH, SS,
                SS, (long)SS * SS, SS, SS,
                10);
        }
        softmax_conv_kernel<<<BB * SS, 256>>>(Praw, Ph);
        // n0n = P @ x  (fp16 HMMA, K=640 -> 20 stages; emits fp16 n0h too)
        {
            dim3 grid(3, 5, BB);
            hmma_gemm_kernel<<<grid, 256>>>(
                Ph, xTh, n0n, n0h,
                KPH, (long)SS * KPH, SS,
                KPH, (long)320 * KPH, 320,
                EE, (long)SS * EE, SS, EE,
                20);
        }

        n0c = n0n; n1c = n1n; n2c = n2n;
    }

    // pack output: n0 | n1 | n2
    cudaMemcpyAsync(out, n0c, (size_t)BB * SS * EE * sizeof(float),
                    cudaMemcpyDeviceToDevice, 0);
    cudaMemcpyAsync(out + (long)BB * SS * EE, n1c, (size_t)BB * HH * sizeof(float),
                    cudaMemcpyDeviceToDevice, 0);
    cudaMemcpyAsync(out + (long)BB * SS * EE + BB * HH, n2c,
                    (size_t)BB * NCC * sizeof(float), cudaMemcpyDeviceToDevice, 0);
}

// round 9
// speedup vs baseline: 4.0833x; 1.1253x over previous
#include <cuda_runtime.h>
#include <cuda_fp16.h>
#include <math.h>
#include <stdint.h>

// Problem constants
#define BB   16
#define SS   600
#define EE   300
#define HH   512
#define NCC  2
#define DD   180000L
#define TT   3

#define KAH  320    // padded K for e-dim (300 -> 320)
#define KPH  640    // padded K for s-dim (600 -> 640)

// fused W1 kernel tiling
#define DSLICE 256
#define HCHUNK 32
#define NCHUNK (HH / HCHUNK)
#define NDBLK  ((int)((DD + DSLICE - 1) / DSLICE))

// ---------------- scratch (device globals) -----------------------------------
__device__ float g_Wx [BB * SS * EE];
__device__ float g_Praw[BB * SS * SS];
__device__ float g_n0a[BB * SS * EE];
__device__ float g_n0b[BB * SS * EE];
__device__ float g_n1a[BB * HH];
__device__ float g_n1b[BB * HH];
__device__ float g_n2a[BB * NCC];
__device__ float g_n2b[BB * NCC];
__device__ float g_g1 [BB * HH];
__device__ __half g_xh  [(size_t)BB * SS * KAH];
__device__ __half g_xTh [(size_t)BB * 320 * KPH];
__device__ __half g_g0h [(size_t)BB * SS * KAH];
__device__ __half g_Ph  [(size_t)BB * SS * KPH];
__device__ __half g_W0h [(size_t)EE * KAH];
__device__ __half g_n0h [(size_t)BB * DD + 512];
__device__ __half g_n1h [BB * HH];

// ---------------- helpers -----------------------------------------------------
__device__ __forceinline__ uint32_t smem_u32(const void* p) {
    uint32_t a;
    asm("{ .reg .u64 t; cvta.to.shared.u64 t, %1; cvt.u32.u64 %0, t; }" : "=r"(a) : "l"(p));
    return a;
}
__device__ __forceinline__ void ldm_x4(uint32_t* r, uint32_t addr) {
    asm volatile("ldmatrix.sync.aligned.m8n8.x4.shared.b16 {%0,%1,%2,%3}, [%4];"
                 : "=r"(r[0]), "=r"(r[1]), "=r"(r[2]), "=r"(r[3]) : "r"(addr));
}
__device__ __forceinline__ void ldm_x4_t(uint32_t* r, uint32_t addr) {
    asm volatile("ldmatrix.sync.aligned.m8n8.x4.trans.shared.b16 {%0,%1,%2,%3}, [%4];"
                 : "=r"(r[0]), "=r"(r[1]), "=r"(r[2]), "=r"(r[3]) : "r"(addr));
}
__device__ __forceinline__ void mma16816(float* c, const uint32_t* a, const uint32_t* b) {
    asm volatile(
        "mma.sync.aligned.m16n8k16.row.col.f32.f16.f16.f32 "
        "{%0,%1,%2,%3}, {%4,%5,%6,%7}, {%8,%9}, {%0,%1,%2,%3};"
        : "+f"(c[0]), "+f"(c[1]), "+f"(c[2]), "+f"(c[3])
        : "r"(a[0]), "r"(a[1]), "r"(a[2]), "r"(a[3]), "r"(b[0]), "r"(b[1]));
}
__device__ __forceinline__ void cp_async16(uint32_t dst, const void* src, int bytes) {
    asm volatile("cp.async.cg.shared.global [%0], [%1], 16, %2;"
                 :: "r"(dst), "l"(src), "r"(bytes));
}
__device__ __forceinline__ void cp_commit() {
    asm volatile("cp.async.commit_group;");
}
template <int N>
__device__ __forceinline__ void cp_wait() {
    asm volatile("cp.async.wait_group %0;" :: "n"(N));
}

// ============ fused per-step W1 kernel (fp16 single-term) ====================
__global__ __launch_bounds__(256, 2)
void fused_w1_kernel(const float* __restrict__ W1,
                     const __half* __restrict__ n1h,
                     const __half* __restrict__ n0h,
                     const float* __restrict__ Wx,
                     float* __restrict__ g1,
                     __half* __restrict__ g0h,
                     float scale)
{
    __shared__ __align__(16) __half tF[HCHUNK][DSLICE + 8];
    __shared__ float g1buf[HCHUNK][17];

    const int t = threadIdx.x, lane = t & 31, wid = t >> 5;
    const long d0 = (long)blockIdx.x * DSLICE;

    uint4 pre[8];

    auto issue_loads = [&](int hc) {
#pragma unroll
        for (int i = 0; i < 8; ++i) {
            int f = t + i * 256;
            int row = f >> 6, c4 = f & 63;
            long d = d0 + (long)c4 * 4;
            if (d + 4 <= DD)
                pre[i] = *(const uint4*)(W1 + (long)(hc * HCHUNK + row) * DD + d);
            else
                pre[i] = make_uint4(0, 0, 0, 0);
        }
    };
    auto store_tiles = [&]() {
#pragma unroll
        for (int i = 0; i < 8; ++i) {
            int f = t + i * 256;
            int row = f >> 6, c4 = f & 63;
            float4 v = *(float4*)&pre[i];
            __half h[4];
            h[0] = __float2half_rn(v.x);
            h[1] = __float2half_rn(v.y);
            h[2] = __float2half_rn(v.z);
            h[3] = __float2half_rn(v.w);
            *(uint2*)&tF[row][c4 * 4] = *(uint2*)h;
        }
    };

    float accg0[8][4] = {};

    issue_loads(0);
    store_tiles();
    for (int i = t; i < HCHUNK * 17; i += 256) ((float*)g1buf)[i] = 0.f;
    __syncthreads();

    for (int hc = 0; hc < NCHUNK; ++hc) {
        if (hc + 1 < NCHUNK) issue_loads(hc + 1);

        if (wid < 4) {
            const int tr_r = lane & 15, tr_c = (lane >> 4) * 8;
            const int ar = lane >> 2, ac = (lane & 3) * 2;
#pragma unroll
            for (int ks = 0; ks < 2; ++ks) {
                int kb = hc * HCHUNK + ks * 16;
                uint32_t ah[4];
                ah[0] = *(const uint32_t*)(n1h + ar * HH + kb + ac);
                ah[1] = *(const uint32_t*)(n1h + (ar + 8) * HH + kb + ac);
                ah[2] = *(const uint32_t*)(n1h + ar * HH + kb + ac + 8);
                ah[3] = *(const uint32_t*)(n1h + (ar + 8) * HH + kb + ac + 8);
#pragma unroll
                for (int q = 0; q < 4; ++q) {
                    uint32_t bf[4];
                    ldm_x4_t(bf, smem_u32(&tF[ks * 16 + tr_r][wid * 64 + q * 16 + tr_c]));
                    mma16816(accg0[q * 2],     ah, &bf[0]);
                    mma16816(accg0[q * 2 + 1], ah, &bf[2]);
                }
            }
        } else {
            const int w = wid - 4;
            const int a_r = lane & 15, a_c = (lane >> 4) * 8;
            float acc1[2][2][4] = {};
#pragma unroll
            for (int ks = 0; ks < 4; ++ks) {
                long dk = d0 + w * 64 + ks * 16;
                uint32_t bh[2][2];
#pragma unroll
                for (int nt = 0; nt < 2; ++nt) {
                    long baddr = (long)(nt * 8 + (lane >> 2)) * DD + dk + (lane & 3) * 2;
                    bh[nt][0] = *(const uint32_t*)(n0h + baddr);
                    bh[nt][1] = *(const uint32_t*)(n0h + baddr + 8);
                }
#pragma unroll
                for (int mt = 0; mt < 2; ++mt) {
                    uint32_t af[4];
                    ldm_x4(af, smem_u32(&tF[mt * 16 + a_r][w * 64 + ks * 16 + a_c]));
#pragma unroll
                    for (int nt = 0; nt < 2; ++nt)
                        mma16816(acc1[mt][nt], af, bh[nt]);
                }
            }
            const int cr = lane >> 2, cc = (lane & 3) * 2;
#pragma unroll
            for (int mt = 0; mt < 2; ++mt)
#pragma unroll
                for (int nt = 0; nt < 2; ++nt) {
                    atomicAdd(&g1buf[mt * 16 + cr][nt * 8 + cc],         acc1[mt][nt][0]);
                    atomicAdd(&g1buf[mt * 16 + cr][nt * 8 + cc + 1],     acc1[mt][nt][1]);
                    atomicAdd(&g1buf[mt * 16 + cr + 8][nt * 8 + cc],     acc1[mt][nt][2]);
                    atomicAdd(&g1buf[mt * 16 + cr + 8][nt * 8 + cc + 1], acc1[mt][nt][3]);
                }
        }
        __syncthreads();

#pragma unroll
        for (int i = 0; i < 2; ++i) {
            int idx = t + i * 256;
            int h = idx >> 4, b = idx & 15;
            float v = g1buf[h][b];
            if (v != 0.f) atomicAdd(&g1[b * HH + hc * HCHUNK + h], v);
            g1buf[h][b] = 0.f;
        }
        if (hc + 1 < NCHUNK) store_tiles();
        __syncthreads();
    }

    if (wid < 4) {
        const int ar = lane >> 2, cc = (lane & 3) * 2;
#pragma unroll
        for (int q = 0; q < 8; ++q) {
            int dn = wid * 64 + q * 8 + cc;
            long d = d0 + dn;
            if (d + 1 < DD) {
                int s = (int)(d / EE), e = (int)(d % EE);
#pragma unroll
                for (int half = 0; half < 2; ++half) {
                    int bb = ar + half * 8;
                    float2 wx = *(const float2*)(Wx + (long)bb * DD + d);
                    __half h[2];
                    h[0] = __float2half_rn((wx.x + accg0[q][half * 2])     * scale);
                    h[1] = __float2half_rn((wx.y + accg0[q][half * 2 + 1]) * scale);
                    *(uint32_t*)&g0h[((long)(bb * SS + s)) * KAH + e] = *(uint32_t*)h;
                }
            }
        }
    }
}

// ---------------- pipelined HMMA GEMM (fp16): C = A · B^T --------------------
// optional fp16 output Ch (own ld, scaled)
__global__ __launch_bounds__(256, 2)
void hmma_gemm_kernel(const __half* __restrict__ A,
                      const __half* __restrict__ B,
                      float* __restrict__ C,
                      __half* __restrict__ Ch,
                      int ldA, long bsA, int rowsA,
                      int ldB, long bsB, int rowsB,
                      int ldC, long bsC, int Mvalid, int Nvalid,
                      int ldCh, float ch_scale,
                      int kchunks)
{
    __shared__ __align__(16) __half As[2][128][40];
    __shared__ __align__(16) __half Bs[2][128][40];
    const int t = threadIdx.x, lane = t & 31, wid = t >> 5;
    const int wm = wid >> 2, wn = wid & 3;
    const int b = blockIdx.z, m0 = blockIdx.y * 128, n0 = blockIdx.x * 128;
    const __half* Ab = A + (long)b * bsA;
    const __half* Bb = B + (long)b * bsB;
    float acc[4][4][4] = {};

    const int l_row = t >> 2, l_q = t & 3;
    auto stage_in = [&](int ch, int buf) {
        long kg = (long)ch * 32 + l_q * 8;
#pragma unroll
        for (int i = 0; i < 2; ++i) {
            int row = l_row + i * 64;
            int ra = m0 + row, rb = n0 + row;
            int ca = (ra < rowsA) ? 16 : 0;
            int cb = (rb < rowsB) ? 16 : 0;
            if (ra >= rowsA) ra = 0;
            if (rb >= rowsB) rb = 0;
            cp_async16(smem_u32(&As[buf][row][l_q * 8]), Ab + (long)ra * ldA + kg, ca);
            cp_async16(smem_u32(&Bs[buf][row][l_q * 8]), Bb + (long)rb * ldB + kg, cb);
        }
    };

    stage_in(0, 0); cp_commit();
    if (kchunks > 1) { stage_in(1, 1); }
    cp_commit();

    const int a_lm = lane & 15;
    const int a_lk = (lane >> 4) * 8;
    const int b_ln = (lane & 7) + ((lane >> 4) & 1) * 8;
    const int b_lk = ((lane >> 3) & 1) * 8;

    for (int ch = 0; ch < kchunks; ++ch) {
        const int buf = ch & 1;
        cp_wait<1>();
        __syncthreads();
#pragma unroll
        for (int ks = 0; ks < 2; ++ks) {
            uint32_t af[4][4], bf[4][2];
#pragma unroll
            for (int mf = 0; mf < 4; ++mf)
                ldm_x4(af[mf], smem_u32(&As[buf][wm * 64 + mf * 16 + a_lm][ks * 16 + a_lk]));
#pragma unroll
            for (int nf2 = 0; nf2 < 2; ++nf2) {
                uint32_t r[4];
                ldm_x4(r, smem_u32(&Bs[buf][wn * 32 + nf2 * 16 + b_ln][ks * 16 + b_lk]));
                bf[nf2 * 2][0] = r[0];     bf[nf2 * 2][1] = r[1];
                bf[nf2 * 2 + 1][0] = r[2]; bf[nf2 * 2 + 1][1] = r[3];
            }
#pragma unroll
            for (int mf = 0; mf < 4; ++mf)
#pragma unroll
                for (int nf = 0; nf < 4; ++nf)
                    mma16816(acc[mf][nf], af[mf], bf[nf]);
        }
        __syncthreads();
        if (ch + 2 < kchunks) stage_in(ch + 2, buf);
        cp_commit();
    }

    float* Cb = C + (long)b * bsC;
    const int mbase = m0 + wm * 64, nbase = n0 + wn * 32;
#pragma unroll
    for (int mf = 0; mf < 4; ++mf) {
#pragma unroll
        for (int nf = 0; nf < 4; ++nf) {
            int m = mbase + mf * 16 + (lane >> 2);
            int n = nbase + nf * 8 + (lane & 3) * 2;
            if (n < Nvalid) {
#pragma unroll
                for (int half = 0; half < 2; ++half) {
                    int mm = m + half * 8;
                    float v0 = acc[mf][nf][half * 2], v1 = acc[mf][nf][half * 2 + 1];
                    if (mm < Mvalid) {
                        *(float2*)&Cb[(long)mm * ldC + n] = make_float2(v0, v1);
                        if (Ch) {
                            __half h[2];
                            h[0] = __float2half_rn(v0 * ch_scale);
                            h[1] = __float2half_rn(v1 * ch_scale);
                            *(uint32_t*)&Ch[(long)b * bsC + (long)mm * ldCh + n] =
                                *(uint32_t*)h;
                        }
                    }
                }
            }
        }
    }
}

// ---------------- conversions -------------------------------------------------
__global__ void conv_x_kernel(const float* __restrict__ x,
                              __half* __restrict__ xh,
                              __half* __restrict__ xTh)
{
    int s = blockIdx.x, b = blockIdx.y, e = threadIdx.x;
    if (s < SS) {
        float v = (e < EE) ? x[((long)b * SS + s) * EE + e] : 0.f;
        __half h = __float2half_rn(v);
        xh[((long)b * SS + s) * KAH + e] = h;
        xTh[((long)b * 320 + e) * KPH + s] = h;
    } else {
        xTh[((long)b * 320 + e) * KPH + s] = __float2half_rn(0.f);
    }
}

__global__ void conv_w0_kernel(const float* __restrict__ W0,
                               __half* __restrict__ W0h)
{
    int f = blockIdx.x, e = threadIdx.x;
    float v = (e < EE) ? W0[f * EE + e] : 0.f;
    W0h[(long)f * KAH + e] = __float2half_rn(v);
}

// ---------------- small kernels ----------------------------------------------
__global__ void init_g1_kernel(const float* __restrict__ b1, const float* __restrict__ n2,
                               const float* __restrict__ W2, float* __restrict__ g1)
{
    int b = blockIdx.x, h = threadIdx.x;
    g1[b * HH + h] = b1[h] + n2[b * NCC] * W2[h] + n2[b * NCC + 1] * W2[HH + h];
}

__global__ void g2_kernel(const float* __restrict__ n1, const float* __restrict__ W2,
                          const float* __restrict__ b2, float* __restrict__ n2n)
{
    int t = threadIdx.x;
    int wid = t >> 5, lane = t & 31;
    int b = wid >> 1, c = wid & 1;
    float s = 0.f;
    for (int h = lane; h < HH; h += 32)
        s += n1[b * HH + h] * W2[c * HH + h];
#pragma unroll
    for (int off = 16; off > 0; off >>= 1)
        s += __shfl_down_sync(0xffffffffu, s, off);
    if (lane == 0) n2n[b * NCC + c] = tanhf(b2[c] + s);
}

__global__ void tanh_n1_kernel(const float* __restrict__ g1, float* __restrict__ n1n,
                               __half* __restrict__ n1h)
{
    int i = blockIdx.x * blockDim.x + threadIdx.x;
    float v = tanhf(g1[i]);
    n1n[i] = v;
    n1h[i] = __float2half_rn(v);
}

__global__ void init_step0_kernel(const float* __restrict__ b1, const float* __restrict__ b2,
                                  float* __restrict__ n1n, float* __restrict__ n2n,
                                  __half* __restrict__ n1h)
{
    int b = blockIdx.x, h = threadIdx.x;
    float v = tanhf(b1[h]);
    n1n[b * HH + h] = v;
    n1h[b * HH + h] = __float2half_rn(v);
    if (h < NCC) n2n[b * NCC + h] = tanhf(b2[h]);
}

// ---------------- softmax: warp-per-row, fused fp16 conversion ---------------
// grid = BB*SS/8 blocks, 256 threads (8 warps, 1 row each)
__global__ __launch_bounds__(256)
void softmax_conv_kernel(const float* __restrict__ Praw, __half* __restrict__ Ph)
{
    const int w = threadIdx.x >> 5, lane = threadIdx.x & 31;
    const long r = (long)blockIdx.x * 8 + w;
    const float* p = Praw + r * SS;
    __half* out = Ph + r * KPH;

    float4 v[5];
    float mx = -INFINITY;
#pragma unroll
    for (int it = 0; it < 5; ++it) {
        int c = lane * 4 + it * 128;
        if (c < SS) {
            v[it] = *(const float4*)(p + c);
            mx = fmaxf(mx, fmaxf(fmaxf(v[it].x, v[it].y), fmaxf(v[it].z, v[it].w)));
        }
    }
#pragma unroll
    for (int off = 16; off > 0; off >>= 1)
        mx = fmaxf(mx, __shfl_xor_sync(0xffffffffu, mx, off));

    float sum = 0.f;
#pragma unroll
    for (int it = 0; it < 5; ++it) {
        int c = lane * 4 + it * 128;
        if (c < SS) {
            v[it].x = expf(v[it].x - mx);
            v[it].y = expf(v[it].y - mx);
            v[it].z = expf(v[it].z - mx);
            v[it].w = expf(v[it].w - mx);
            sum += v[it].x + v[it].y + v[it].z + v[it].w;
        }
    }
#pragma unroll
    for (int off = 16; off > 0; off >>= 1)
        sum += __shfl_xor_sync(0xffffffffu, sum, off);
    float inv = 1.f / sum;

#pragma unroll
    for (int it = 0; it < 5; ++it) {
        int c = lane * 4 + it * 128;
        if (c < SS) {
            __half h[4];
            h[0] = __float2half_rn(v[it].x * inv);
            h[1] = __float2half_rn(v[it].y * inv);
            h[2] = __float2half_rn(v[it].z * inv);
            h[3] = __float2half_rn(v[it].w * inv);
            *(uint2*)&out[c] = *(uint2*)h;
        } else if (c < KPH) {
            *(uint2*)&out[c] = make_uint2(0, 0);
        }
    }
}

// ---------------- host driver ------------------------------------------------
static float* sym_addr_f(const void* sym)
{
    void* p = nullptr;
    cudaGetSymbolAddress(&p, sym);
    return (float*)p;
}
static __half* sym_addr_h(const void* sym)
{
    void* p = nullptr;
    cudaGetSymbolAddress(&p, sym);
    return (__half*)p;
}

extern "C" void kernel_launch(void* const* d_in, const int* in_sizes, int n_in,
                              void* d_out, int out_size)
{
    const float* x   = (const float*)d_in[0];
    const float* W0  = (const float*)d_in[5];
    const float* W1  = (const float*)d_in[6];
    const float* b1  = (const float*)d_in[7];
    const float* W2  = (const float*)d_in[8];
    const float* b2  = (const float*)d_in[9];
    float* out = (float*)d_out;

    float* Wx   = sym_addr_f(g_Wx);
    float* Praw = sym_addr_f(g_Praw);
    float* g1   = sym_addr_f(g_g1);
    float* n0buf[2] = { sym_addr_f(g_n0a), sym_addr_f(g_n0b) };
    float* n1buf[2] = { sym_addr_f(g_n1a), sym_addr_f(g_n1b) };
    float* n2buf[2] = { sym_addr_f(g_n2a), sym_addr_f(g_n2b) };
    __half* xh   = sym_addr_h(g_xh);
    __half* xTh  = sym_addr_h(g_xTh);
    __half* g0h  = sym_addr_h(g_g0h);
    __half* Ph   = sym_addr_h(g_Ph);
    __half* W0h  = sym_addr_h(g_W0h);
    __half* n0h  = sym_addr_h(g_n0h);
    __half* n1h  = sym_addr_h(g_n1h);

    const float scale = 1.0f / sqrtf((float)EE);

    // one-time conversions
    {
        dim3 g(640, BB);
        conv_x_kernel<<<g, 320>>>(x, xh, xTh);
    }
    conv_w0_kernel<<<EE, 320>>>(W0, W0h);

    // Wx = x @ W0^T (fp16 HMMA); epilogue also emits g0h = fp16(scale*Wx)
    {
        dim3 grid(3, 75, 1);
        hmma_gemm_kernel<<<grid, 256>>>(
            xh, W0h, Wx, g0h,
            KAH, 0, BB * SS,
            KAH, 0, EE,
            EE, 0, BB * SS, EE,
            KAH, scale,
            10);
    }

    const float* n0c = nullptr;
    const float* n1c = nullptr;
    const float* n2c = nullptr;

    for (int step = 0; step < TT; ++step) {
        float* n0n = n0buf[step & 1];
        float* n1n = n1buf[step & 1];
        float* n2n = n2buf[step & 1];

        if (step == 0) {
            init_step0_kernel<<<BB, HH>>>(b1, b2, n1n, n2n, n1h);
            // g0h already = fp16(scale*Wx) from the Wx GEMM epilogue
        } else {
            init_g1_kernel<<<BB, HH>>>(b1, n2c, W2, g1);
            g2_kernel<<<1, 1024>>>(n1c, W2, b2, n2n);
            fused_w1_kernel<<<NDBLK, 256>>>(W1, n1h, n0h, Wx, g1, g0h, scale);
            tanh_n1_kernel<<<BB, HH>>>(g1, n1n, n1h);
        }

        // scores = (scale*g0) @ x^T
        {
            dim3 grid(5, 5, BB);
            hmma_gemm_kernel<<<grid, 256>>>(
                g0h, xh, Praw, nullptr,
                KAH, (long)SS * KAH, SS,
                KAH, (long)SS * KAH, SS,
                SS, (long)SS * SS, SS, SS,
                0, 1.0f,
                10);
        }
        softmax_conv_kernel<<<BB * SS / 8, 256>>>(Praw, Ph);
        // n0n = P @ x  (also emits fp16 n0h)
        {
            dim3 grid(3, 5, BB);
            hmma_gemm_kernel<<<grid, 256>>>(
                Ph, xTh, n0n, n0h,
                KPH, (long)SS * KPH, SS,
                KPH, (long)320 * KPH, 320,
                EE, (long)SS * EE, SS, EE,
                EE, 1.0f,
                20);
        }

        n0c = n0n; n1c = n1n; n2c = n2n;
    }

    // pack output: n0 | n1 | n2
    cudaMemcpyAsync(out, n0c, (size_t)BB * SS * EE * sizeof(float),
                    cudaMemcpyDeviceToDevice, 0);
    cudaMemcpyAsync(out + (long)BB * SS * EE, n1c, (size_t)BB * HH * sizeof(float),
                    cudaMemcpyDeviceToDevice, 0);
    cudaMemcpyAsync(out + (long)BB * SS * EE + BB * HH, n2c,
                    (size_t)BB * NCC * sizeof(float), cudaMemcpyDeviceToDevice, 0);
}